// round 1
// baseline (speedup 1.0000x reference)
#include <cuda_runtime.h>
#include <math.h>

#define NB    16
#define CIN_  384
#define CG    768
#define FEAT_ 192
#define HH    64
#define WW    64

// Scratch (device globals; no allocations allowed)
__device__ float g_h[NB * CG * HH * WW];          // shuffled gate inputs (b, c', y, w)  ~201MB
__device__ float g_W0t[CIN_ * CG];                // i2s tap0, [ic][oc'] (rows shuffled)
__device__ float g_W1t[CIN_ * CG];                // i2s tap1 masked, [ic][oc']
__device__ float g_w1r[FEAT_ * 3 * CG];           // s2s weights [(kf*3+t)][ocmap]
__device__ float g_wskt[FEAT_ * CIN_];            // skip weights [ci][co]
__device__ float g_hstate[2][NB * FEAT_ * WW];    // LSTM hidden, double buffered
__device__ float g_cstate[NB * FEAT_ * WW];       // LSTM cell
__device__ float g_outh[NB * FEAT_ * HH * WW];    // scan outputs  ~50MB

__device__ __forceinline__ float sigf(float v) { return 1.0f / (1.0f + __expf(-v)); }

// ---------------------------------------------------------------------------
// Weight prep: fold shuffle + masks into layouts optimized for the GEMM kernels
// shuffle: h_shuf[c'] = h[c], c' = q*192 + p*64 + fl  <->  c = p*256 + q*64 + fl
// s2s oc reorder: ocmap = ftile*32 + gate*8 + j  <->  oc = gate*192 + ftile*8 + j
// ---------------------------------------------------------------------------
__global__ void prep_kernel(const float* __restrict__ w_i2s,
                            const float* __restrict__ w_s2s,
                            const float* __restrict__ w_skip) {
    int idx = blockIdx.x * blockDim.x + threadIdx.x;
    if (idx < CIN_ * CG) {
        int ic = idx / CG, cp = idx % CG;
        int q = cp / 192, p = (cp % 192) / 64, fl = cp % 64;
        int c = p * 256 + q * 64 + fl;                 // original (pre-shuffle) channel
        const float* wb = w_i2s + ((long)c * CIN_ + ic) * 3;
        g_W0t[idx] = wb[0];                            // left tap: always enabled
        g_W1t[idx] = (p >= (ic / 128)) ? wb[1] : 0.f;  // center tap: og >= ig
        // right tap is fully masked to 0
    }
    if (idx < FEAT_ * 3 * CG) {
        int ocmap = idx % CG;
        int kt = idx / CG;           // kt = kf*3 + t
        int kf = kt / 3, t = kt % 3;
        int ftile = ocmap / 32, r = ocmap % 32, gate = r / 8, j = r % 8;
        int oc = gate * FEAT_ + ftile * 8 + j;
        g_w1r[idx] = w_s2s[((long)oc * FEAT_ + kf) * 3 + t];
    }
    if (idx < FEAT_ * CIN_) {
        int ci = idx / CIN_, co = idx % CIN_;
        g_wskt[idx] = w_skip[co * FEAT_ + ci];   // mask handled by K-bound (block-aligned)
    }
}

__global__ void init_kernel() {
    int i = blockIdx.x * blockDim.x + threadIdx.x;
    if (i < NB * FEAT_ * WW) {
        g_hstate[0][i] = 0.f;
        g_cstate[i] = 0.f;
    }
}

// ---------------------------------------------------------------------------
// i2s: h[b,oc',y,w] = sum_ic W0[oc',ic]*x[b,ic,y,w-1] + W1[oc',ic]*x[b,ic,y,w]
// block = 64 oc x 64 w for one (b,y); thread = 8 oc x 4 w
// ---------------------------------------------------------------------------
__global__ void __launch_bounds__(128) i2s_kernel(const float* __restrict__ x) {
    __shared__ float xs[32][72];     // [kc][w+1], halo zero-padded
    __shared__ float ws0[32][64];    // [kc][oc]
    __shared__ float ws1[32][64];

    int row = blockIdx.y;
    int b = row >> 6, y = row & 63;
    int OC0 = blockIdx.x * 64;
    int tid = threadIdx.x;
    int tx = tid & 15, ty = tid >> 4;      // tx: 16 w-groups of 4, ty: 8 oc-groups of 8

    float acc[8][4];
#pragma unroll
    for (int j = 0; j < 8; j++)
#pragma unroll
        for (int i = 0; i < 4; i++) acc[j][i] = 0.f;

    const float* xrow = x + (long)b * CIN_ * HH * WW + y * WW;

    for (int kt = 0; kt < 12; kt++) {
        int ic0 = kt * 32;
        for (int i = tid; i < 32 * 66; i += 128) {
            int r = i / 66, wp = i % 66;
            int w = wp - 1;
            float v = 0.f;
            if (w >= 0 && w < WW) v = xrow[(long)(ic0 + r) * HH * WW + w];
            xs[r][wp] = v;
        }
        for (int i = tid; i < 2048; i += 128) {
            int r = i >> 6, oc = i & 63;
            ws0[r][oc] = g_W0t[(ic0 + r) * CG + OC0 + oc];
            ws1[r][oc] = g_W1t[(ic0 + r) * CG + OC0 + oc];
        }
        __syncthreads();
#pragma unroll 4
        for (int kc = 0; kc < 32; kc++) {
            float4 xv = *(const float4*)&xs[kc][tx * 4];
            float x4 = xs[kc][tx * 4 + 4];
            float xm[5] = {xv.x, xv.y, xv.z, xv.w, x4};
            float4 a0 = *(const float4*)&ws0[kc][ty * 8];
            float4 b0 = *(const float4*)&ws0[kc][ty * 8 + 4];
            float4 a1 = *(const float4*)&ws1[kc][ty * 8];
            float4 b1 = *(const float4*)&ws1[kc][ty * 8 + 4];
            float w0v[8] = {a0.x, a0.y, a0.z, a0.w, b0.x, b0.y, b0.z, b0.w};
            float w1v[8] = {a1.x, a1.y, a1.z, a1.w, b1.x, b1.y, b1.z, b1.w};
#pragma unroll
            for (int j = 0; j < 8; j++)
#pragma unroll
                for (int i = 0; i < 4; i++)
                    acc[j][i] += w0v[j] * xm[i] + w1v[j] * xm[i + 1];
        }
        __syncthreads();
    }

    float* hb = g_h + ((long)(b * CG + OC0) * HH + y) * WW;
#pragma unroll
    for (int j = 0; j < 8; j++) {
        float4 v = make_float4(acc[j][0], acc[j][1], acc[j][2], acc[j][3]);
        *(float4*)&hb[(long)(ty * 8 + j) * HH * WW + tx * 4] = v;
    }
}

// ---------------------------------------------------------------------------
// One LSTM row: s = conv1d(hprev, w1, pad 1) + h_row; gates; update c, h.
// block = 32 s-rows (4 gates x 8 hidden ch) x 64 w for one b; thread = 4 oc x 4 w
// grid (24 ftiles, 16 b) = 384 blocks
// ---------------------------------------------------------------------------
__global__ void __launch_bounds__(128) lstm_row_kernel(int y, int rpar) {
    __shared__ union SU {
        struct { float hp[32][72]; float ws[32][3][32]; } g;
        float sbuf[32][68];
    } sm;

    int b = blockIdx.y;
    int ftile = blockIdx.x;          // 0..23, F0 = ftile*8
    int F0 = ftile * 8;
    int tid = threadIdx.x;
    int tx = tid & 15, ty = tid >> 4;   // ty: 8 groups of 4 oc-rows

    float acc[4][4];
#pragma unroll
    for (int j = 0; j < 4; j++)
#pragma unroll
        for (int i = 0; i < 4; i++) acc[j][i] = 0.f;

    const float* hprev = g_hstate[rpar] + (long)b * FEAT_ * WW;

    for (int kt = 0; kt < 6; kt++) {
        int f0k = kt * 32;
        for (int i = tid; i < 32 * 66; i += 128) {
            int r = i / 66, wp = i % 66;
            int w = wp - 1;
            float v = 0.f;
            if (w >= 0 && w < WW) v = hprev[(f0k + r) * WW + w];
            sm.g.hp[r][wp] = v;
        }
        for (int i = tid; i < 32 * 3 * 32; i += 128) {
            int kc = i / 96, rem = i % 96, t = rem / 32, ocr = rem % 32;
            sm.g.ws[kc][t][ocr] = g_w1r[((f0k + kc) * 3 + t) * CG + ftile * 32 + ocr];
        }
        __syncthreads();
#pragma unroll 4
        for (int kc = 0; kc < 32; kc++) {
            float4 xv = *(const float4*)&sm.g.hp[kc][tx * 4];
            float x4 = sm.g.hp[kc][tx * 4 + 4];
            float x5 = sm.g.hp[kc][tx * 4 + 5];
            float xm[6] = {xv.x, xv.y, xv.z, xv.w, x4, x5};
            float4 w0 = *(const float4*)&sm.g.ws[kc][0][ty * 4];
            float4 w1 = *(const float4*)&sm.g.ws[kc][1][ty * 4];
            float4 w2 = *(const float4*)&sm.g.ws[kc][2][ty * 4];
            float wt0[4] = {w0.x, w0.y, w0.z, w0.w};
            float wt1[4] = {w1.x, w1.y, w1.z, w1.w};
            float wt2[4] = {w2.x, w2.y, w2.z, w2.w};
#pragma unroll
            for (int j = 0; j < 4; j++)
#pragma unroll
                for (int i = 0; i < 4; i++)
                    acc[j][i] += wt0[j] * xm[i] + wt1[j] * xm[i + 1] + wt2[j] * xm[i + 2];
        }
        __syncthreads();
    }

    // add gate-input row h[b, gate*192 + F0 + jj, y, :]
#pragma unroll
    for (int j = 0; j < 4; j++) {
        int ocr = ty * 4 + j;
        int gate = ocr >> 3, jj = ocr & 7;
        const float* hrow = g_h + ((long)(b * CG + gate * FEAT_ + F0 + jj) * HH + y) * WW + tx * 4;
        float4 hv = *(const float4*)hrow;
        acc[j][0] += hv.x; acc[j][1] += hv.y; acc[j][2] += hv.z; acc[j][3] += hv.w;
    }

    // stage s into smem (union reuse; all hp/ws reads already fenced by last sync)
#pragma unroll
    for (int j = 0; j < 4; j++) {
        *(float4*)&sm.sbuf[ty * 4 + j][tx * 4] =
            make_float4(acc[j][0], acc[j][1], acc[j][2], acc[j][3]);
    }
    __syncthreads();

    // pointwise gate update: 8 f x 64 w, 128 threads x 4 w each
    int fl = tid >> 4;            // 0..7
    int w0 = (tid & 15) * 4;
    int base = (b * FEAT_ + F0 + fl) * WW + w0;

    float4 ov = *(const float4*)&sm.sbuf[fl][w0];
    float4 fv = *(const float4*)&sm.sbuf[8 + fl][w0];
    float4 iv = *(const float4*)&sm.sbuf[16 + fl][w0];
    float4 gv = *(const float4*)&sm.sbuf[24 + fl][w0];
    float4 cv = *(const float4*)&g_cstate[base];

    float so[4] = {sigf(ov.x), sigf(ov.y), sigf(ov.z), sigf(ov.w)};
    float sf[4] = {sigf(fv.x), sigf(fv.y), sigf(fv.z), sigf(fv.w)};
    float si[4] = {sigf(iv.x), sigf(iv.y), sigf(iv.z), sigf(iv.w)};
    float sg[4] = {sigf(gv.x), sigf(gv.y), sigf(gv.z), sigf(gv.w)};
    float cold[4] = {cv.x, cv.y, cv.z, cv.w};
    float cn[4], hn[4];
#pragma unroll
    for (int i = 0; i < 4; i++) {
        cn[i] = sf[i] * cold[i] + si[i] * sg[i];
        hn[i] = so[i] * tanhf(cn[i]);
    }
    *(float4*)&g_cstate[base] = make_float4(cn[0], cn[1], cn[2], cn[3]);
    *(float4*)&g_hstate[rpar ^ 1][base] = make_float4(hn[0], hn[1], hn[2], hn[3]);
    *(float4*)&g_outh[((b * FEAT_ + F0 + fl) * HH + y) * WW + w0] =
        make_float4(hn[0], hn[1], hn[2], hn[3]);
}

// ---------------------------------------------------------------------------
// skip: out = x + b_skip + W_skip_masked @ out_h  (mask is block-aligned -> K bound)
// block = 64 co x 64 w for one (b,y); thread = 8 co x 4 w
// ---------------------------------------------------------------------------
__global__ void __launch_bounds__(128) skip_kernel(const float* __restrict__ x,
                                                   const float* __restrict__ b_skip,
                                                   float* __restrict__ out) {
    __shared__ float os[32][68];
    __shared__ float ws[32][64];

    int row = blockIdx.y;
    int b = row >> 6, y = row & 63;
    int OC0 = blockIdx.x * 64;
    int Ktot = ((OC0 >> 7) + 1) * 64;    // 64 / 128 / 192
    int tid = threadIdx.x;
    int tx = tid & 15, ty = tid >> 4;

    float acc[8][4];
#pragma unroll
    for (int j = 0; j < 8; j++)
#pragma unroll
        for (int i = 0; i < 4; i++) acc[j][i] = 0.f;

    const float* oh = g_outh + (long)b * FEAT_ * HH * WW + y * WW;

    for (int kt = 0; kt * 32 < Ktot; kt++) {
        int c0 = kt * 32;
        for (int i = tid; i < 32 * 64; i += 128) {
            int r = i >> 6, w = i & 63;
            os[r][w] = oh[(long)(c0 + r) * HH * WW + w];
        }
        for (int i = tid; i < 2048; i += 128) {
            int r = i >> 6, oc = i & 63;
            ws[r][oc] = g_wskt[(c0 + r) * CIN_ + OC0 + oc];
        }
        __syncthreads();
#pragma unroll 8
        for (int kc = 0; kc < 32; kc++) {
            float4 xv = *(const float4*)&os[kc][tx * 4];
            float xm[4] = {xv.x, xv.y, xv.z, xv.w};
            float4 wa = *(const float4*)&ws[kc][ty * 8];
            float4 wb = *(const float4*)&ws[kc][ty * 8 + 4];
            float wv[8] = {wa.x, wa.y, wa.z, wa.w, wb.x, wb.y, wb.z, wb.w};
#pragma unroll
            for (int j = 0; j < 8; j++)
#pragma unroll
                for (int i = 0; i < 4; i++)
                    acc[j][i] += wv[j] * xm[i];
        }
        __syncthreads();
    }

#pragma unroll
    for (int j = 0; j < 8; j++) {
        int co = OC0 + ty * 8 + j;
        float bs = b_skip[co];
        long off = ((long)(b * CIN_ + co) * HH + y) * WW + tx * 4;
        float4 xin = *(const float4*)&x[off];
        float4 r = make_float4(xin.x + bs + acc[j][0], xin.y + bs + acc[j][1],
                               xin.z + bs + acc[j][2], xin.w + bs + acc[j][3]);
        *(float4*)&out[off] = r;
    }
}

// ---------------------------------------------------------------------------
extern "C" void kernel_launch(void* const* d_in, const int* in_sizes, int n_in,
                              void* d_out, int out_size) {
    const float* x      = (const float*)d_in[0];
    const float* w_i2s  = (const float*)d_in[1];
    const float* w_s2s  = (const float*)d_in[2];
    const float* w_skip = (const float*)d_in[3];
    const float* b_skip = (const float*)d_in[4];
    float* out = (float*)d_out;

    prep_kernel<<<(FEAT_ * 3 * CG + 255) / 256, 256>>>(w_i2s, w_s2s, w_skip);
    init_kernel<<<(NB * FEAT_ * WW + 255) / 256, 256>>>();
    i2s_kernel<<<dim3(12, NB * HH), 128>>>(x);
    for (int y = 0; y < HH; y++)
        lstm_row_kernel<<<dim3(24, NB), 128>>>(y, y & 1);
    skip_kernel<<<dim3(6, NB * HH), 128>>>(x, b_skip, out);
}

// round 2
// speedup vs baseline: 1.1562x; 1.1562x over previous
#include <cuda_runtime.h>
#include <math.h>

#define NB    16
#define CIN_  384
#define CG    768
#define FEAT_ 192
#define HH    64
#define WW    64

// Scratch (device globals; no allocations allowed)
__device__ float g_h[NB * CG * HH * WW];          // shuffled gate inputs (b, c', y, w)
__device__ float g_W0t[CIN_ * CG];                // i2s tap0, [ic][oc'] (rows shuffled)
__device__ float g_W1t[CIN_ * CG];                // i2s tap1 masked, [ic][oc']
__device__ float g_w1r[FEAT_ * 3 * CG];           // s2s weights [(kf*3+t)][ocmap]
__device__ float g_wskt[FEAT_ * CIN_];            // skip weights [ci][co]
__device__ float g_hstate[2][NB * FEAT_ * WW];    // LSTM hidden, double buffered
__device__ float g_outh[NB * FEAT_ * HH * WW];    // scan outputs
__device__ unsigned g_rowbar[NB * 32];            // per-b row barriers (128B apart)

__device__ __forceinline__ float sigf(float v) { return 1.0f / (1.0f + __expf(-v)); }
__device__ __forceinline__ float tanhfast(float x) {
    float y; asm("tanh.approx.f32 %0, %1;" : "=f"(y) : "f"(x)); return y;
}

// ---------------------------------------------------------------------------
// Weight prep: fold shuffle + masks into GEMM-friendly layouts
// shuffle: c' = q*192 + p*64 + fl  <->  c = p*256 + q*64 + fl
// s2s oc reorder: ocmap = ftile*32 + gate*8 + j  <->  oc = gate*192 + ftile*8 + j
// ---------------------------------------------------------------------------
__global__ void prep_kernel(const float* __restrict__ w_i2s,
                            const float* __restrict__ w_s2s,
                            const float* __restrict__ w_skip) {
    int idx = blockIdx.x * blockDim.x + threadIdx.x;
    if (idx < CIN_ * CG) {
        int ic = idx / CG, cp = idx % CG;
        int q = cp / 192, p = (cp % 192) / 64, fl = cp % 64;
        int c = p * 256 + q * 64 + fl;
        const float* wb = w_i2s + ((long)c * CIN_ + ic) * 3;
        g_W0t[idx] = wb[0];
        g_W1t[idx] = (p >= (ic / 128)) ? wb[1] : 0.f;
    }
    if (idx < FEAT_ * 3 * CG) {
        int ocmap = idx % CG;
        int kt = idx / CG;           // kt = kf*3 + t
        int kf = kt / 3, t = kt % 3;
        int ftile = ocmap / 32, r = ocmap % 32, gate = r / 8, j = r % 8;
        int oc = gate * FEAT_ + ftile * 8 + j;
        g_w1r[idx] = w_s2s[((long)oc * FEAT_ + kf) * 3 + t];
    }
    if (idx < FEAT_ * CIN_) {
        int ci = idx / CIN_, co = idx % CIN_;
        g_wskt[idx] = w_skip[co * FEAT_ + ci];
    }
}

__global__ void init_kernel() {
    int i = blockIdx.x * blockDim.x + threadIdx.x;
    if (i < NB * FEAT_ * WW) g_hstate[0][i] = 0.f;
    if (i < NB * 32) g_rowbar[i] = 0u;
}

// ---------------------------------------------------------------------------
// i2s: h[b,oc',y,w] = sum_ic W0[oc',ic]*x[b,ic,y,w-1] + W1[oc',ic]*x[b,ic,y,w]
// ---------------------------------------------------------------------------
__global__ void __launch_bounds__(128) i2s_kernel(const float* __restrict__ x) {
    __shared__ float xs[32][68];     // [kc][w+1], left halo zero
    __shared__ float ws0[32][64];
    __shared__ float ws1[32][64];

    int row = blockIdx.y;
    int b = row >> 6, y = row & 63;
    int OC0 = blockIdx.x * 64;
    int tid = threadIdx.x;
    int tx = tid & 15, ty = tid >> 4;

    if (tid < 32) xs[tid][0] = 0.f;   // constant left halo

    float acc[8][4];
#pragma unroll
    for (int j = 0; j < 8; j++)
#pragma unroll
        for (int i = 0; i < 4; i++) acc[j][i] = 0.f;

    const float* xrow = x + (long)b * CIN_ * HH * WW + y * WW;

    for (int kt = 0; kt < 12; kt++) {
        int ic0 = kt * 32;
#pragma unroll
        for (int i = tid; i < 2048; i += 128) {
            int r = i >> 6, w = i & 63;
            xs[r][w + 1] = xrow[(long)(ic0 + r) * HH * WW + w];
        }
#pragma unroll
        for (int i = tid; i < 2048; i += 128) {
            int r = i >> 6, oc = i & 63;
            ws0[r][oc] = g_W0t[(ic0 + r) * CG + OC0 + oc];
            ws1[r][oc] = g_W1t[(ic0 + r) * CG + OC0 + oc];
        }
        __syncthreads();
#pragma unroll 4
        for (int kc = 0; kc < 32; kc++) {
            float4 xv = *(const float4*)&xs[kc][tx * 4];
            float x4 = xs[kc][tx * 4 + 4];
            float xm[5] = {xv.x, xv.y, xv.z, xv.w, x4};
            float4 a0 = *(const float4*)&ws0[kc][ty * 8];
            float4 b0 = *(const float4*)&ws0[kc][ty * 8 + 4];
            float4 a1 = *(const float4*)&ws1[kc][ty * 8];
            float4 b1 = *(const float4*)&ws1[kc][ty * 8 + 4];
            float w0v[8] = {a0.x, a0.y, a0.z, a0.w, b0.x, b0.y, b0.z, b0.w};
            float w1v[8] = {a1.x, a1.y, a1.z, a1.w, b1.x, b1.y, b1.z, b1.w};
#pragma unroll
            for (int j = 0; j < 8; j++)
#pragma unroll
                for (int i = 0; i < 4; i++)
                    acc[j][i] += w0v[j] * xm[i] + w1v[j] * xm[i + 1];
        }
        __syncthreads();
    }

    float* hb = g_h + ((long)(b * CG + OC0) * HH + y) * WW;
#pragma unroll
    for (int j = 0; j < 8; j++) {
        float4 v = make_float4(acc[j][0], acc[j][1], acc[j][2], acc[j][3]);
        *(float4*)&hb[(long)(ty * 8 + j) * HH * WW + tx * 4] = v;
    }
}

// ---------------------------------------------------------------------------
// Persistent LSTM scan: one kernel, 64 rows, per-b software barrier per row.
// grid (24 ftiles, 16 b), block 128. Each CTA: 32 s-rows (4 gates x 8 hc) x 64 w.
// Cell state lives in registers. All 384 CTAs co-resident (21KB smem, 128 thr).
// ---------------------------------------------------------------------------
__global__ void __launch_bounds__(128) lstm_scan_kernel() {
    __shared__ float hp[32][68];     // [kc][w+1], both halos constant zero
    __shared__ float wsf[3072];      // [kc*3+t][32 ocr]; reused as sbuf (needs 2176)

    int b = blockIdx.y;
    int ftile = blockIdx.x;
    int F0 = ftile * 8;
    int tid = threadIdx.x;
    int tx = tid & 15, ty = tid >> 4;
    int fl = tid >> 4;               // pointwise mapping: 8 hidden ch
    int w0 = (tid & 15) * 4;

    float (*sbuf)[68] = (float(*)[68])wsf;

    // constant halos (sbuf overlay never touches hp region)
    if (tid < 64) hp[tid & 31][(tid >> 5) ? 65 : 0] = 0.f;

    float creg[4] = {0.f, 0.f, 0.f, 0.f};

    // prefetch gate-input row 0
    float4 hv4[4];
#pragma unroll
    for (int j = 0; j < 4; j++) {
        int ocr = ty * 4 + j, gate = ocr >> 3, jj = ocr & 7;
        hv4[j] = *(const float4*)&g_h[((long)(b * CG + gate * FEAT_ + F0 + jj) * HH + 0) * WW + tx * 4];
    }
    __syncthreads();

    unsigned* bar = &g_rowbar[b * 32];

    for (int y = 0; y < HH; y++) {
        const float* hs_r = g_hstate[y & 1] + (long)b * FEAT_ * WW;

        float acc[4][4];
#pragma unroll
        for (int j = 0; j < 4; j++)
#pragma unroll
            for (int i = 0; i < 4; i++) acc[j][i] = 0.f;

        for (int kt = 0; kt < 6; kt++) {
            int f0k = kt * 32;
#pragma unroll
            for (int i = tid; i < 2048; i += 128) {
                int r = i >> 6, w = i & 63;
                hp[r][w + 1] = hs_r[(f0k + r) * WW + w];
            }
#pragma unroll
            for (int i = tid; i < 3072; i += 128) {
                int rw = i >> 5, ocr = i & 31;
                wsf[i] = g_w1r[(f0k * 3 + rw) * CG + ftile * 32 + ocr];
            }
            __syncthreads();
#pragma unroll 4
            for (int kc = 0; kc < 32; kc++) {
                float4 xv = *(const float4*)&hp[kc][tx * 4];
                float x4 = hp[kc][tx * 4 + 4];
                float x5 = hp[kc][tx * 4 + 5];
                float xm[6] = {xv.x, xv.y, xv.z, xv.w, x4, x5};
                float4 w0v = *(const float4*)&wsf[(kc * 3 + 0) * 32 + ty * 4];
                float4 w1v = *(const float4*)&wsf[(kc * 3 + 1) * 32 + ty * 4];
                float4 w2v = *(const float4*)&wsf[(kc * 3 + 2) * 32 + ty * 4];
                float wt0[4] = {w0v.x, w0v.y, w0v.z, w0v.w};
                float wt1[4] = {w1v.x, w1v.y, w1v.z, w1v.w};
                float wt2[4] = {w2v.x, w2v.y, w2v.z, w2v.w};
#pragma unroll
                for (int j = 0; j < 4; j++)
#pragma unroll
                    for (int i = 0; i < 4; i++)
                        acc[j][i] += wt0[j] * xm[i] + wt1[j] * xm[i + 1] + wt2[j] * xm[i + 2];
            }
            __syncthreads();
        }

        // add gate-input row (prefetched), stage s into sbuf (overlays wsf)
#pragma unroll
        for (int j = 0; j < 4; j++) {
            sbuf[ty * 4 + j][tx * 4 + 0] = acc[j][0] + hv4[j].x;
            sbuf[ty * 4 + j][tx * 4 + 1] = acc[j][1] + hv4[j].y;
            sbuf[ty * 4 + j][tx * 4 + 2] = acc[j][2] + hv4[j].z;
            sbuf[ty * 4 + j][tx * 4 + 3] = acc[j][3] + hv4[j].w;
        }

        // prefetch next row's gate inputs (independent; hides HBM behind barrier)
        if (y < HH - 1) {
#pragma unroll
            for (int j = 0; j < 4; j++) {
                int ocr = ty * 4 + j, gate = ocr >> 3, jj = ocr & 7;
                hv4[j] = *(const float4*)&g_h[((long)(b * CG + gate * FEAT_ + F0 + jj) * HH + (y + 1)) * WW + tx * 4];
            }
        }
        __syncthreads();

        // pointwise gate update (each thread owns fixed (fl, w0..w0+3) + creg)
        float4 ov = *(const float4*)&sbuf[fl][w0];
        float4 fv = *(const float4*)&sbuf[8 + fl][w0];
        float4 iv = *(const float4*)&sbuf[16 + fl][w0];
        float4 gv = *(const float4*)&sbuf[24 + fl][w0];

        float so[4] = {sigf(ov.x), sigf(ov.y), sigf(ov.z), sigf(ov.w)};
        float sf[4] = {sigf(fv.x), sigf(fv.y), sigf(fv.z), sigf(fv.w)};
        float si[4] = {sigf(iv.x), sigf(iv.y), sigf(iv.z), sigf(iv.w)};
        float sg[4] = {sigf(gv.x), sigf(gv.y), sigf(gv.z), sigf(gv.w)};
        float hn[4];
#pragma unroll
        for (int i = 0; i < 4; i++) {
            creg[i] = sf[i] * creg[i] + si[i] * sg[i];
            hn[i] = so[i] * tanhfast(creg[i]);
        }
        int base = (b * FEAT_ + F0 + fl) * WW + w0;
        float4 hout = make_float4(hn[0], hn[1], hn[2], hn[3]);
        *(float4*)&g_hstate[(y & 1) ^ 1][base] = hout;
        *(float4*)&g_outh[((b * FEAT_ + F0 + fl) * HH + y) * WW + w0] = hout;

        // per-b barrier: all 24 ftile CTAs of this b finished row y
        if (y < HH - 1) {
            __syncthreads();                 // all CTA stores issued
            if (tid == 0) {
                __threadfence();             // make h visible gpu-wide
                atomicAdd(bar, 1u);
                unsigned target = 24u * (unsigned)(y + 1);
                while (atomicAdd(bar, 0u) < target) __nanosleep(32);
                __threadfence();
            }
            __syncthreads();                 // broadcast happens-before to CTA
        }
    }
}

// ---------------------------------------------------------------------------
// skip: out = x + b_skip + W_skip_masked @ out_h (block-aligned mask -> K bound)
// ---------------------------------------------------------------------------
__global__ void __launch_bounds__(128) skip_kernel(const float* __restrict__ x,
                                                   const float* __restrict__ b_skip,
                                                   float* __restrict__ out) {
    __shared__ float os[32][68];
    __shared__ float ws[32][64];

    int row = blockIdx.y;
    int b = row >> 6, y = row & 63;
    int OC0 = blockIdx.x * 64;
    int Ktot = ((OC0 >> 7) + 1) * 64;    // 64 / 128 / 192
    int tid = threadIdx.x;
    int tx = tid & 15, ty = tid >> 4;

    float acc[8][4];
#pragma unroll
    for (int j = 0; j < 8; j++)
#pragma unroll
        for (int i = 0; i < 4; i++) acc[j][i] = 0.f;

    const float* oh = g_outh + (long)b * FEAT_ * HH * WW + y * WW;

    for (int kt = 0; kt * 32 < Ktot; kt++) {
        int c0 = kt * 32;
#pragma unroll
        for (int i = tid; i < 2048; i += 128) {
            int r = i >> 6, w = i & 63;
            os[r][w] = oh[(long)(c0 + r) * HH * WW + w];
        }
#pragma unroll
        for (int i = tid; i < 2048; i += 128) {
            int r = i >> 6, oc = i & 63;
            ws[r][oc] = g_wskt[(c0 + r) * CIN_ + OC0 + oc];
        }
        __syncthreads();
#pragma unroll 8
        for (int kc = 0; kc < 32; kc++) {
            float4 xv = *(const float4*)&os[kc][tx * 4];
            float xm[4] = {xv.x, xv.y, xv.z, xv.w};
            float4 wa = *(const float4*)&ws[kc][ty * 8];
            float4 wb = *(const float4*)&ws[kc][ty * 8 + 4];
            float wv[8] = {wa.x, wa.y, wa.z, wa.w, wb.x, wb.y, wb.z, wb.w};
#pragma unroll
            for (int j = 0; j < 8; j++)
#pragma unroll
                for (int i = 0; i < 4; i++)
                    acc[j][i] += wv[j] * xm[i];
        }
        __syncthreads();
    }

#pragma unroll
    for (int j = 0; j < 8; j++) {
        int co = OC0 + ty * 8 + j;
        float bs = b_skip[co];
        long off = ((long)(b * CIN_ + co) * HH + y) * WW + tx * 4;
        float4 xin = *(const float4*)&x[off];
        float4 r = make_float4(xin.x + bs + acc[j][0], xin.y + bs + acc[j][1],
                               xin.z + bs + acc[j][2], xin.w + bs + acc[j][3]);
        *(float4*)&out[off] = r;
    }
}

// ---------------------------------------------------------------------------
extern "C" void kernel_launch(void* const* d_in, const int* in_sizes, int n_in,
                              void* d_out, int out_size) {
    const float* x      = (const float*)d_in[0];
    const float* w_i2s  = (const float*)d_in[1];
    const float* w_s2s  = (const float*)d_in[2];
    const float* w_skip = (const float*)d_in[3];
    const float* b_skip = (const float*)d_in[4];
    float* out = (float*)d_out;

    prep_kernel<<<(FEAT_ * 3 * CG + 255) / 256, 256>>>(w_i2s, w_s2s, w_skip);
    init_kernel<<<(NB * FEAT_ * WW + 255) / 256, 256>>>();
    i2s_kernel<<<dim3(12, NB * HH), 128>>>(x);
    lstm_scan_kernel<<<dim3(24, NB), 128>>>();
    skip_kernel<<<dim3(6, NB * HH), 128>>>(x, b_skip, out);
}

// round 4
// speedup vs baseline: 2.9627x; 2.5624x over previous
#include <cuda_runtime.h>
#include <math.h>
#include <stdint.h>

#define NB    16
#define CIN_  384
#define CG    768
#define FEAT_ 192
#define HH    64
#define WW    64

// Scratch (device globals; no allocations allowed)
__device__ float g_h[NB * CG * HH * WW];          // shuffled gate inputs (b, c', y, w)
__device__ float g_Wa[2][CG * CIN_];              // i2s weights [tap][oc'][ic], masked, tf32-rounded
__device__ float g_w1r[FEAT_ * 3 * CG];           // s2s weights [(kf*3+t)][ocmap], tf32-rounded
__device__ float g_wskt[FEAT_ * CIN_];            // skip weights [ci][co]
__device__ float g_hstate[2][NB * FEAT_ * WW];    // LSTM hidden, double buffered
__device__ float g_outh[NB * FEAT_ * HH * WW];    // scan outputs
__device__ unsigned g_rowbar[NB * 32];            // per-bpair row barriers

__device__ __forceinline__ float sigf(float v) { return 1.0f / (1.0f + __expf(-v)); }
__device__ __forceinline__ float tanhfast(float x) {
    float y; asm("tanh.approx.f32 %0, %1;" : "=f"(y) : "f"(x)); return y;
}
__device__ __forceinline__ float tf32r(float x) {
    uint32_t u; asm("cvt.rna.tf32.f32 %0, %1;" : "=r"(u) : "f"(x));
    return __uint_as_float(u);
}
#define F2U(x) __float_as_uint(x)

// m16n8k8 tf32 mma: A row-major fragment, B col-major fragment, f32 accum
__device__ __forceinline__ void mma8(float* d, uint32_t a0, uint32_t a1, uint32_t a2, uint32_t a3,
                                     uint32_t b0, uint32_t b1) {
    asm volatile("mma.sync.aligned.m16n8k8.row.col.f32.tf32.tf32.f32 "
                 "{%0,%1,%2,%3}, {%4,%5,%6,%7}, {%8,%9}, {%0,%1,%2,%3};"
                 : "+f"(d[0]), "+f"(d[1]), "+f"(d[2]), "+f"(d[3])
                 : "r"(a0), "r"(a1), "r"(a2), "r"(a3), "r"(b0), "r"(b1));
}

// ---------------------------------------------------------------------------
// Weight prep: fold shuffle + masks, round to tf32
// shuffle: c' = q*192 + p*64 + fl  <->  c = p*256 + q*64 + fl
// s2s oc reorder: ocmap = ftile*32 + gate*8 + j <-> oc = gate*192 + ftile*8 + j
// ---------------------------------------------------------------------------
__global__ void prep_kernel(const float* __restrict__ w_i2s,
                            const float* __restrict__ w_s2s,
                            const float* __restrict__ w_skip) {
    int idx = blockIdx.x * blockDim.x + threadIdx.x;
    if (idx < CG * CIN_) {
        int ocp = idx / CIN_, ic = idx % CIN_;
        int q = ocp / 192, p = (ocp % 192) / 64, fl = ocp % 64;
        int c = p * 256 + q * 64 + fl;
        const float* wb = w_i2s + ((long)c * CIN_ + ic) * 3;
        g_Wa[0][idx] = tf32r(wb[0]);
        g_Wa[1][idx] = (p >= (ic / 128)) ? tf32r(wb[1]) : 0.f;
    }
    if (idx < FEAT_ * 3 * CG) {
        int ocmap = idx % CG;
        int kt = idx / CG;
        int kf = kt / 3, t = kt % 3;
        int ftile = ocmap / 32, r = ocmap % 32, gate = r / 8, j = r % 8;
        int oc = gate * FEAT_ + ftile * 8 + j;
        g_w1r[idx] = tf32r(w_s2s[((long)oc * FEAT_ + kf) * 3 + t]);
    }
    if (idx < FEAT_ * CIN_) {
        int ci = idx / CIN_, co = idx % CIN_;
        g_wskt[idx] = w_skip[co * FEAT_ + ci];
    }
}

__global__ void init_kernel() {
    int i = blockIdx.x * blockDim.x + threadIdx.x;
    if (i < NB * FEAT_ * WW) g_hstate[0][i] = 0.f;
    if (i < NB * 32) g_rowbar[i] = 0u;
}

// ---------------------------------------------------------------------------
// i2s via mma.sync tf32. Per CTA: M=128 oc', N=128 (2 rows x 64 w), K=384 x 2 taps.
// out[oc,w] = W0[oc,:]@x[:,w-1] + W1[oc,:]@x[:,w]; shift via halo'd B smem.
// 256 threads = 8 warps; warp w: m-tile w (16 oc) x all 16 n-tiles.
// smem: wa[2][128][36] (A, conflict-free), xs[2][32][72] (B, conflict-free)
// ---------------------------------------------------------------------------
#define I2S_SMEM 55296

__global__ void __launch_bounds__(256, 2) i2s_mma_kernel(const float* __restrict__ x) {
    extern __shared__ float sm[];
    float* wa = sm;               // [t][oc][kk] stride 36
    float* xs = sm + 9216;        // [yr][k][i] stride 72, i=w+1 (halo at 0)

    int tid = threadIdx.x, lane = tid & 31, wid = tid >> 5;
    int OC0 = blockIdx.x * 128;
    int b = blockIdx.y >> 5, y0 = (blockIdx.y & 31) * 2;

    if (tid < 64) xs[(tid >> 5) * 2304 + (tid & 31) * 72] = 0.f;   // left halo

    float d[16][4];
#pragma unroll
    for (int nt = 0; nt < 16; nt++)
#pragma unroll
        for (int i = 0; i < 4; i++) d[nt][i] = 0.f;

    const float* xb = x + (long)b * CIN_ * HH * WW;
    int m0 = wid * 16;

    for (int c = 0; c < 12; c++) {
        int k0 = c * 32;
        __syncthreads();
#pragma unroll
        for (int i = tid; i < 2048; i += 256) {           // weights (float4)
            int t = i >> 10, r = i & 1023, oc = r >> 3, kk = r & 7;
            float4 v = *(const float4*)&g_Wa[t][(OC0 + oc) * CIN_ + k0 + kk * 4];
            *(float4*)&wa[t * 4608 + oc * 36 + kk * 4] = v;
        }
#pragma unroll
        for (int i = tid; i < 4096; i += 256) {           // x (scalar, tf32-rounded)
            int yr = i >> 11, r = i & 2047, k = r >> 6, w = r & 63;
            float v = xb[((long)(k0 + k) * HH + y0 + yr) * WW + w];
            xs[yr * 2304 + k * 72 + w + 1] = tf32r(v);
        }
        __syncthreads();
#pragma unroll
        for (int k8 = 0; k8 < 4; k8++) {
#pragma unroll
            for (int t = 0; t < 2; t++) {
                const float* wp = wa + t * 4608 + (m0 + (lane >> 2)) * 36 + k8 * 8 + (lane & 3);
                uint32_t a0 = F2U(wp[0]);
                uint32_t a1 = F2U(wp[8 * 36]);
                uint32_t a2 = F2U(wp[4]);
                uint32_t a3 = F2U(wp[8 * 36 + 4]);
#pragma unroll
                for (int nt = 0; nt < 16; nt++) {
                    const float* hb = xs + (nt >> 3) * 2304 + (k8 * 8 + (lane & 3)) * 72
                                      + (nt & 7) * 8 + (lane >> 2) + t;
                    mma8(d[nt], a0, a1, a2, a3, F2U(hb[0]), F2U(hb[4 * 72]));
                }
            }
        }
    }

    // epilogue: float2 stores (cols (c,c+1) per thread)
    int ocl = OC0 + wid * 16 + (lane >> 2);
#pragma unroll
    for (int nt = 0; nt < 16; nt++) {
        int y = y0 + (nt >> 3);
        int w = (nt & 7) * 8 + (lane & 3) * 2;
        float* p0 = &g_h[(((long)b * CG + ocl) * HH + y) * WW + w];
        *(float2*)p0 = make_float2(d[nt][0], d[nt][1]);
        *(float2*)(p0 + (long)8 * HH * WW) = make_float2(d[nt][2], d[nt][3]);
    }
}

// ---------------------------------------------------------------------------
// Persistent LSTM scan with mma.sync tf32.
// grid (24 ftiles, 8 b-pairs) = 192 CTAs, 128 thr, ~112KB smem -> 2 CTA/SM,
// all co-resident. Full s2s weights loaded once per CTA. Each CTA: 2 b's x
// 32 s-rows x 64 w per image row; per-bpair atomic barrier per row.
// ---------------------------------------------------------------------------
#define SCAN_SMEM 111872

__global__ void __launch_bounds__(128, 2) lstm_scan_mma() {
    extern __shared__ float sm[];
    float* wst  = sm;                        // [576][33]: [kt=(k*3+t)][ocr]
    float* hp   = sm + 19008;                // [2][32][72], i=w+1, halos 0/65
    float* sbuf = sm + 19008 + 4608;         // [2][32][68]

    int tid = threadIdx.x, lane = tid & 31, wid = tid >> 5;
    int ftile = blockIdx.x, bpair = blockIdx.y;
    int F0 = ftile * 8;
    int fl = tid >> 4, w0 = (tid & 15) * 4;
    int m0 = (wid & 1) * 16, n0 = (wid >> 1) * 32;

    // full weight tile, once
    for (int i = tid; i < 18432; i += 128) {
        int kt = i >> 5, r = i & 31;
        wst[kt * 33 + r] = g_w1r[(long)kt * CG + ftile * 32 + r];
    }
    // hp halos (cols 0 and 65), once
    {
        int bb = tid >> 6, k = tid & 31, hcol = ((tid >> 5) & 1) ? 65 : 0;
        hp[bb * 2304 + k * 72 + hcol] = 0.f;
    }

    float creg[2][4] = {{0.f,0.f,0.f,0.f},{0.f,0.f,0.f,0.f}};
    float4 hv[2][4];
#pragma unroll
    for (int bb = 0; bb < 2; bb++)
#pragma unroll
        for (int g = 0; g < 4; g++)
            hv[bb][g] = *(const float4*)&g_h[(((long)(bpair*2+bb) * CG + g*FEAT_ + F0 + fl) * HH + 0) * WW + w0];
    __syncthreads();

    unsigned* bar = &g_rowbar[bpair * 32];

    for (int y = 0; y < HH; y++) {
        float d[2][4][4];
#pragma unroll
        for (int bb = 0; bb < 2; bb++)
#pragma unroll
            for (int nt = 0; nt < 4; nt++)
#pragma unroll
                for (int i = 0; i < 4; i++) d[bb][nt][i] = 0.f;

        const float* hsr = g_hstate[y & 1];

        for (int ch = 0; ch < 6; ch++) {
            int f0k = ch * 32;
            __syncthreads();
#pragma unroll
            for (int i = tid; i < 4096; i += 128) {
                int bb = i >> 11, r = i & 2047, k = r >> 6, w = r & 63;
                float v = hsr[((bpair*2+bb) * FEAT_ + f0k + k) * WW + w];
                hp[bb * 2304 + k * 72 + w + 1] = tf32r(v);
            }
            __syncthreads();
#pragma unroll
            for (int k8 = 0; k8 < 4; k8++) {
#pragma unroll
                for (int t = 0; t < 3; t++) {
                    int kt0 = (f0k + k8 * 8 + (lane & 3)) * 3 + t;
                    const float* wp = wst + kt0 * 33 + m0 + (lane >> 2);
                    uint32_t a0 = F2U(wp[0]);
                    uint32_t a1 = F2U(wp[8]);
                    uint32_t a2 = F2U(wp[12 * 33]);       // k+4 -> kt+12
                    uint32_t a3 = F2U(wp[12 * 33 + 8]);
#pragma unroll
                    for (int bb = 0; bb < 2; bb++) {
                        const float* hb = hp + bb * 2304 + (k8 * 8 + (lane & 3)) * 72
                                          + n0 + (lane >> 2) + t;
#pragma unroll
                        for (int nt = 0; nt < 4; nt++)
                            mma8(d[bb][nt], a0, a1, a2, a3,
                                 F2U(hb[nt * 8]), F2U(hb[4 * 72 + nt * 8]));
                    }
                }
            }
        }

        // stage raw s into sbuf
#pragma unroll
        for (int bb = 0; bb < 2; bb++)
#pragma unroll
            for (int nt = 0; nt < 4; nt++) {
                int r = m0 + (lane >> 2);
                int cc = n0 + nt * 8 + (lane & 3) * 2;
                *(float2*)&sbuf[bb * 2176 + r * 68 + cc] = make_float2(d[bb][nt][0], d[bb][nt][1]);
                *(float2*)&sbuf[bb * 2176 + (r + 8) * 68 + cc] = make_float2(d[bb][nt][2], d[bb][nt][3]);
            }
        __syncthreads();

        // pointwise gate update (thread owns (fl, w0..w0+3) per bb; c in regs)
#pragma unroll
        for (int bb = 0; bb < 2; bb++) {
            float* sb = sbuf + bb * 2176;
            float4 ov = *(const float4*)&sb[fl * 68 + w0];
            float4 fv = *(const float4*)&sb[(8 + fl) * 68 + w0];
            float4 iv = *(const float4*)&sb[(16 + fl) * 68 + w0];
            float4 gv = *(const float4*)&sb[(24 + fl) * 68 + w0];
            float so[4] = {sigf(ov.x + hv[bb][0].x), sigf(ov.y + hv[bb][0].y),
                           sigf(ov.z + hv[bb][0].z), sigf(ov.w + hv[bb][0].w)};
            float sf[4] = {sigf(fv.x + hv[bb][1].x), sigf(fv.y + hv[bb][1].y),
                           sigf(fv.z + hv[bb][1].z), sigf(fv.w + hv[bb][1].w)};
            float si[4] = {sigf(iv.x + hv[bb][2].x), sigf(iv.y + hv[bb][2].y),
                           sigf(iv.z + hv[bb][2].z), sigf(iv.w + hv[bb][2].w)};
            float sg[4] = {sigf(gv.x + hv[bb][3].x), sigf(gv.y + hv[bb][3].y),
                           sigf(gv.z + hv[bb][3].z), sigf(gv.w + hv[bb][3].w)};
            float hn[4];
#pragma unroll
            for (int i = 0; i < 4; i++) {
                creg[bb][i] = sf[i] * creg[bb][i] + si[i] * sg[i];
                hn[i] = so[i] * tanhfast(creg[bb][i]);
            }
            int base = ((bpair*2+bb) * FEAT_ + F0 + fl) * WW + w0;
            float4 hout = make_float4(hn[0], hn[1], hn[2], hn[3]);
            *(float4*)&g_hstate[(y & 1) ^ 1][base] = hout;
            *(float4*)&g_outh[(((bpair*2+bb) * FEAT_ + F0 + fl) * HH + y) * WW + w0] = hout;
        }

        if (y < HH - 1) {
            // prefetch next row gate inputs (hides HBM behind barrier)
#pragma unroll
            for (int bb = 0; bb < 2; bb++)
#pragma unroll
                for (int g = 0; g < 4; g++)
                    hv[bb][g] = *(const float4*)&g_h[(((long)(bpair*2+bb) * CG + g*FEAT_ + F0 + fl) * HH + (y+1)) * WW + w0];
            __syncthreads();
            if (tid == 0) {
                __threadfence();
                atomicAdd(bar, 1u);
                unsigned target = 24u * (unsigned)(y + 1);
                while (atomicAdd(bar, 0u) < target) __nanosleep(32);
                __threadfence();
            }
            __syncthreads();
        }
    }
}

// ---------------------------------------------------------------------------
// skip: out = x + b_skip + W_skip_masked @ out_h (block-aligned mask -> K bound)
// ---------------------------------------------------------------------------
__global__ void __launch_bounds__(128) skip_kernel(const float* __restrict__ x,
                                                   const float* __restrict__ b_skip,
                                                   float* __restrict__ out) {
    __shared__ float os[32][68];
    __shared__ float ws[32][64];

    int row = blockIdx.y;
    int b = row >> 6, y = row & 63;
    int OC0 = blockIdx.x * 64;
    int Ktot = ((OC0 >> 7) + 1) * 64;
    int tid = threadIdx.x;
    int tx = tid & 15, ty = tid >> 4;

    float acc[8][4];
#pragma unroll
    for (int j = 0; j < 8; j++)
#pragma unroll
        for (int i = 0; i < 4; i++) acc[j][i] = 0.f;

    const float* oh = g_outh + (long)b * FEAT_ * HH * WW + y * WW;

    for (int kt = 0; kt * 32 < Ktot; kt++) {
        int c0 = kt * 32;
#pragma unroll
        for (int i = tid; i < 2048; i += 128) {
            int r = i >> 6, w = i & 63;
            os[r][w] = oh[(long)(c0 + r) * HH * WW + w];
        }
#pragma unroll
        for (int i = tid; i < 2048; i += 128) {
            int r = i >> 6, oc = i & 63;
            ws[r][oc] = g_wskt[(c0 + r) * CIN_ + OC0 + oc];
        }
        __syncthreads();
#pragma unroll 8
        for (int kc = 0; kc < 32; kc++) {
            float4 xv = *(const float4*)&os[kc][tx * 4];
            float xm[4] = {xv.x, xv.y, xv.z, xv.w};
            float4 wa = *(const float4*)&ws[kc][ty * 8];
            float4 wb = *(const float4*)&ws[kc][ty * 8 + 4];
            float wv[8] = {wa.x, wa.y, wa.z, wa.w, wb.x, wb.y, wb.z, wb.w};
#pragma unroll
            for (int j = 0; j < 8; j++)
#pragma unroll
                for (int i = 0; i < 4; i++)
                    acc[j][i] += wv[j] * xm[i];
        }
        __syncthreads();
    }

#pragma unroll
    for (int j = 0; j < 8; j++) {
        int co = OC0 + ty * 8 + j;
        float bs = b_skip[co];
        long off = ((long)(b * CIN_ + co) * HH + y) * WW + tx * 4;
        float4 xin = *(const float4*)&x[off];
        float4 r = make_float4(xin.x + bs + acc[j][0], xin.y + bs + acc[j][1],
                               xin.z + bs + acc[j][2], xin.w + bs + acc[j][3]);
        *(float4*)&out[off] = r;
    }
}

// ---------------------------------------------------------------------------
extern "C" void kernel_launch(void* const* d_in, const int* in_sizes, int n_in,
                              void* d_out, int out_size) {
    const float* x      = (const float*)d_in[0];
    const float* w_i2s  = (const float*)d_in[1];
    const float* w_s2s  = (const float*)d_in[2];
    const float* w_skip = (const float*)d_in[3];
    const float* b_skip = (const float*)d_in[4];
    float* out = (float*)d_out;

    cudaFuncSetAttribute(i2s_mma_kernel, cudaFuncAttributeMaxDynamicSharedMemorySize, I2S_SMEM);
    cudaFuncSetAttribute(lstm_scan_mma, cudaFuncAttributeMaxDynamicSharedMemorySize, SCAN_SMEM);

    prep_kernel<<<(FEAT_ * 3 * CG + 255) / 256, 256>>>(w_i2s, w_s2s, w_skip);
    init_kernel<<<(NB * FEAT_ * WW + 255) / 256, 256>>>();
    i2s_mma_kernel<<<dim3(6, 512), 256, I2S_SMEM>>>(x);
    lstm_scan_mma<<<dim3(24, 8), 128, SCAN_SMEM>>>();
    skip_kernel<<<dim3(6, NB * HH), 128>>>(x, b_skip, out);
}

// round 5
// speedup vs baseline: 3.1031x; 1.0474x over previous
#include <cuda_runtime.h>
#include <math.h>
#include <stdint.h>

#define NB    16
#define CIN_  384
#define CG    768
#define FEAT_ 192
#define HH    64
#define WW    64

// Scratch (device globals; no allocations allowed)
__device__ float g_h[NB * CG * HH * WW];          // shuffled gate inputs (b, c', y, w)
__device__ float g_Wa[2][CG * CIN_];              // i2s weights [tap][oc'][ic], masked, tf32-rounded
__device__ float g_w1r[FEAT_ * 3 * CG];           // s2s weights [(kf*3+t)][ocmap], tf32-rounded
__device__ float g_wskt2[CIN_ * FEAT_];           // skip weights [co][ci], tf32-rounded
__device__ float g_hstate[2][NB * FEAT_ * WW];    // LSTM hidden, double buffered
__device__ float g_outh[NB * FEAT_ * HH * WW];    // scan outputs (tf32-rounded)
__device__ unsigned g_rowbar[NB * 32];            // per-bpair row barriers

__device__ __forceinline__ float sigf(float v) { return 1.0f / (1.0f + __expf(-v)); }
__device__ __forceinline__ float tanhfast(float x) {
    float y; asm("tanh.approx.f32 %0, %1;" : "=f"(y) : "f"(x)); return y;
}
__device__ __forceinline__ float tf32r(float x) {
    uint32_t u; asm("cvt.rna.tf32.f32 %0, %1;" : "=r"(u) : "f"(x));
    return __uint_as_float(u);
}
__device__ __forceinline__ uint32_t tf32u(float x) {
    uint32_t u; asm("cvt.rna.tf32.f32 %0, %1;" : "=r"(u) : "f"(x));
    return u;
}
__device__ __forceinline__ uint32_t smem_u32(const void* p) {
    uint32_t a;
    asm("{ .reg .u64 t; cvta.to.shared.u64 t, %1; cvt.u32.u64 %0, t; }" : "=r"(a) : "l"(p));
    return a;
}
#define F2U(x) __float_as_uint(x)
#define CP_ASYNC16(dst, src) \
    asm volatile("cp.async.cg.shared.global [%0], [%1], 16;" :: "r"(dst), "l"(src) : "memory")
#define CP_COMMIT() asm volatile("cp.async.commit_group;" ::: "memory")
#define CP_WAIT1()  asm volatile("cp.async.wait_group 1;" ::: "memory")
#define CP_WAIT0()  asm volatile("cp.async.wait_group 0;" ::: "memory")

// m16n8k8 tf32 mma: A row-major fragment, B col-major fragment, f32 accum
__device__ __forceinline__ void mma8(float* d, uint32_t a0, uint32_t a1, uint32_t a2, uint32_t a3,
                                     uint32_t b0, uint32_t b1) {
    asm volatile("mma.sync.aligned.m16n8k8.row.col.f32.tf32.tf32.f32 "
                 "{%0,%1,%2,%3}, {%4,%5,%6,%7}, {%8,%9}, {%0,%1,%2,%3};"
                 : "+f"(d[0]), "+f"(d[1]), "+f"(d[2]), "+f"(d[3])
                 : "r"(a0), "r"(a1), "r"(a2), "r"(a3), "r"(b0), "r"(b1));
}

// ---------------------------------------------------------------------------
// Weight prep: fold shuffle + masks, round to tf32
// ---------------------------------------------------------------------------
__global__ void prep_kernel(const float* __restrict__ w_i2s,
                            const float* __restrict__ w_s2s,
                            const float* __restrict__ w_skip) {
    int idx = blockIdx.x * blockDim.x + threadIdx.x;
    if (idx < CG * CIN_) {
        int ocp = idx / CIN_, ic = idx % CIN_;
        int q = ocp / 192, p = (ocp % 192) / 64, fl = ocp % 64;
        int c = p * 256 + q * 64 + fl;
        const float* wb = w_i2s + ((long)c * CIN_ + ic) * 3;
        g_Wa[0][idx] = tf32r(wb[0]);
        g_Wa[1][idx] = (p >= (ic / 128)) ? tf32r(wb[1]) : 0.f;
    }
    if (idx < FEAT_ * 3 * CG) {
        int ocmap = idx % CG;
        int kt = idx / CG;
        int kf = kt / 3, t = kt % 3;
        int ftile = ocmap / 32, r = ocmap % 32, gate = r / 8, j = r % 8;
        int oc = gate * FEAT_ + ftile * 8 + j;
        g_w1r[idx] = tf32r(w_s2s[((long)oc * FEAT_ + kf) * 3 + t]);
    }
    if (idx < CIN_ * FEAT_) {
        g_wskt2[idx] = tf32r(w_skip[idx]);   // already [co][ci]
    }
}

__global__ void init_kernel() {
    int i = blockIdx.x * blockDim.x + threadIdx.x;
    if (i < NB * FEAT_ * WW) g_hstate[0][i] = 0.f;
    if (i < NB * 32) g_rowbar[i] = 0u;
}

// ---------------------------------------------------------------------------
// i2s via mma.sync tf32 (unchanged from R4).
// ---------------------------------------------------------------------------
#define I2S_SMEM 55296

__global__ void __launch_bounds__(256, 2) i2s_mma_kernel(const float* __restrict__ x) {
    extern __shared__ float sm[];
    float* wa = sm;               // [t][oc][kk] stride 36
    float* xs = sm + 9216;        // [yr][k][i] stride 72, i=w+1 (halo at 0)

    int tid = threadIdx.x, lane = tid & 31, wid = tid >> 5;
    int OC0 = blockIdx.x * 128;
    int b = blockIdx.y >> 5, y0 = (blockIdx.y & 31) * 2;

    if (tid < 64) xs[(tid >> 5) * 2304 + (tid & 31) * 72] = 0.f;   // left halo

    float d[16][4];
#pragma unroll
    for (int nt = 0; nt < 16; nt++)
#pragma unroll
        for (int i = 0; i < 4; i++) d[nt][i] = 0.f;

    const float* xb = x + (long)b * CIN_ * HH * WW;
    int m0 = wid * 16;

    for (int c = 0; c < 12; c++) {
        int k0 = c * 32;
        __syncthreads();
#pragma unroll
        for (int i = tid; i < 2048; i += 256) {
            int t = i >> 10, r = i & 1023, oc = r >> 3, kk = r & 7;
            float4 v = *(const float4*)&g_Wa[t][(OC0 + oc) * CIN_ + k0 + kk * 4];
            *(float4*)&wa[t * 4608 + oc * 36 + kk * 4] = v;
        }
#pragma unroll
        for (int i = tid; i < 4096; i += 256) {
            int yr = i >> 11, r = i & 2047, k = r >> 6, w = r & 63;
            float v = xb[((long)(k0 + k) * HH + y0 + yr) * WW + w];
            xs[yr * 2304 + k * 72 + w + 1] = tf32r(v);
        }
        __syncthreads();
#pragma unroll
        for (int k8 = 0; k8 < 4; k8++) {
#pragma unroll
            for (int t = 0; t < 2; t++) {
                const float* wp = wa + t * 4608 + (m0 + (lane >> 2)) * 36 + k8 * 8 + (lane & 3);
                uint32_t a0 = F2U(wp[0]);
                uint32_t a1 = F2U(wp[8 * 36]);
                uint32_t a2 = F2U(wp[4]);
                uint32_t a3 = F2U(wp[8 * 36 + 4]);
#pragma unroll
                for (int nt = 0; nt < 16; nt++) {
                    const float* hb = xs + (nt >> 3) * 2304 + (k8 * 8 + (lane & 3)) * 72
                                      + (nt & 7) * 8 + (lane >> 2) + t;
                    mma8(d[nt], a0, a1, a2, a3, F2U(hb[0]), F2U(hb[4 * 72]));
                }
            }
        }
    }

    int ocl = OC0 + wid * 16 + (lane >> 2);
#pragma unroll
    for (int nt = 0; nt < 16; nt++) {
        int y = y0 + (nt >> 3);
        int w = (nt & 7) * 8 + (lane & 3) * 2;
        float* p0 = &g_h[(((long)b * CG + ocl) * HH + y) * WW + w];
        *(float2*)p0 = make_float2(d[nt][0], d[nt][1]);
        *(float2*)(p0 + (long)8 * HH * WW) = make_float2(d[nt][2], d[nt][3]);
    }
}

// ---------------------------------------------------------------------------
// Persistent LSTM scan, mma.sync tf32, cp.async double-buffered hp staging.
// grid (24, 8) = 192 CTAs, 128 thr, 110.6KB smem -> 2 CTA/SM co-resident.
// hp layout per buf: [bb][k][72], data cols 4..67 (16B-aligned), halos 3 & 68.
// tf32 rounding applied at B-fragment read.
// ---------------------------------------------------------------------------
#define SCAN_SMEM ((19008 + 9216) * 4)

__global__ void __launch_bounds__(128, 2) lstm_scan_mma() {
    extern __shared__ float sm[];
    float* wst = sm;                         // [576][33]
    float* hpb = sm + 19008;                 // 2 bufs x 4608 floats
    float* sbuf = hpb;                       // overlay buf0: [2][32][68] (4352 <= 4608)

    int tid = threadIdx.x, lane = tid & 31, wid = tid >> 5;
    int ftile = blockIdx.x, bpair = blockIdx.y;
    int F0 = ftile * 8;
    int fl = tid >> 4, w0 = (tid & 15) * 4;
    int m0 = (wid & 1) * 16, n0 = (wid >> 1) * 32;

    for (int i = tid; i < 18432; i += 128) {
        int kt = i >> 5, r = i & 31;
        wst[kt * 33 + r] = g_w1r[(long)kt * CG + ftile * 32 + r];
    }

    float creg[2][4] = {{0.f,0.f,0.f,0.f},{0.f,0.f,0.f,0.f}};
    float4 hv[2][4];
#pragma unroll
    for (int bb = 0; bb < 2; bb++)
#pragma unroll
        for (int g = 0; g < 4; g++)
            hv[bb][g] = *(const float4*)&g_h[(((long)(bpair*2+bb) * CG + g*FEAT_ + F0 + fl) * HH + 0) * WW + w0];
    __syncthreads();

    unsigned* bar = &g_rowbar[bpair * 32];

    for (int y = 0; y < HH; y++) {
        const float* hsr = g_hstate[y & 1];

        auto issue_chunk = [&](int ch, int buf) {
            float* dst = hpb + buf * 4608;
            if (tid < 64) { dst[tid * 72 + 3] = 0.f; dst[tid * 72 + 68] = 0.f; }
            int f0k = ch * 32;
#pragma unroll
            for (int j = 0; j < 8; j++) {
                int i = tid + j * 128;
                int bb = i >> 9, r = i & 511, k = r >> 4, w4 = r & 15;
                uint32_t da = smem_u32(dst + bb * 2304 + k * 72 + 4 + w4 * 4);
                const float* sa = hsr + ((bpair*2+bb) * FEAT_ + f0k + k) * WW + w4 * 4;
                CP_ASYNC16(da, sa);
            }
        };

        float d[2][4][4];
#pragma unroll
        for (int bb = 0; bb < 2; bb++)
#pragma unroll
            for (int nt = 0; nt < 4; nt++)
#pragma unroll
                for (int i = 0; i < 4; i++) d[bb][nt][i] = 0.f;

        issue_chunk(0, 0);
        CP_COMMIT();

        for (int ch = 0; ch < 6; ch++) {
            if (ch < 5) { issue_chunk(ch + 1, (ch + 1) & 1); CP_COMMIT(); CP_WAIT1(); }
            else CP_WAIT0();
            __syncthreads();

            float* hbb = hpb + (ch & 1) * 4608;
            int f0k = ch * 32;
#pragma unroll
            for (int k8 = 0; k8 < 4; k8++) {
#pragma unroll
                for (int t = 0; t < 3; t++) {
                    int kt0 = (f0k + k8 * 8 + (lane & 3)) * 3 + t;
                    const float* wp = wst + kt0 * 33 + m0 + (lane >> 2);
                    uint32_t a0 = F2U(wp[0]);
                    uint32_t a1 = F2U(wp[8]);
                    uint32_t a2 = F2U(wp[12 * 33]);
                    uint32_t a3 = F2U(wp[12 * 33 + 8]);
#pragma unroll
                    for (int bb = 0; bb < 2; bb++) {
                        const float* hb = hbb + bb * 2304 + (k8 * 8 + (lane & 3)) * 72
                                          + 3 + n0 + (lane >> 2) + t;
#pragma unroll
                        for (int nt = 0; nt < 4; nt++)
                            mma8(d[bb][nt], a0, a1, a2, a3,
                                 tf32u(hb[nt * 8]), tf32u(hb[4 * 72 + nt * 8]));
                    }
                }
            }
            if (ch < 5) __syncthreads();
        }

        // stage raw s into sbuf (overlays buf0; chunk5 mma read only buf1)
#pragma unroll
        for (int bb = 0; bb < 2; bb++)
#pragma unroll
            for (int nt = 0; nt < 4; nt++) {
                int r = m0 + (lane >> 2);
                int cc = n0 + nt * 8 + (lane & 3) * 2;
                *(float2*)&sbuf[bb * 2176 + r * 68 + cc] = make_float2(d[bb][nt][0], d[bb][nt][1]);
                *(float2*)&sbuf[bb * 2176 + (r + 8) * 68 + cc] = make_float2(d[bb][nt][2], d[bb][nt][3]);
            }
        __syncthreads();

        // pointwise gate update
#pragma unroll
        for (int bb = 0; bb < 2; bb++) {
            float* sb = sbuf + bb * 2176;
            float4 ov = *(const float4*)&sb[fl * 68 + w0];
            float4 fv = *(const float4*)&sb[(8 + fl) * 68 + w0];
            float4 iv = *(const float4*)&sb[(16 + fl) * 68 + w0];
            float4 gv = *(const float4*)&sb[(24 + fl) * 68 + w0];
            float so[4] = {sigf(ov.x + hv[bb][0].x), sigf(ov.y + hv[bb][0].y),
                           sigf(ov.z + hv[bb][0].z), sigf(ov.w + hv[bb][0].w)};
            float sf[4] = {sigf(fv.x + hv[bb][1].x), sigf(fv.y + hv[bb][1].y),
                           sigf(fv.z + hv[bb][1].z), sigf(fv.w + hv[bb][1].w)};
            float si[4] = {sigf(iv.x + hv[bb][2].x), sigf(iv.y + hv[bb][2].y),
                           sigf(iv.z + hv[bb][2].z), sigf(iv.w + hv[bb][2].w)};
            float sg[4] = {sigf(gv.x + hv[bb][3].x), sigf(gv.y + hv[bb][3].y),
                           sigf(gv.z + hv[bb][3].z), sigf(gv.w + hv[bb][3].w)};
            float hn[4];
#pragma unroll
            for (int i = 0; i < 4; i++) {
                creg[bb][i] = sf[i] * creg[bb][i] + si[i] * sg[i];
                hn[i] = so[i] * tanhfast(creg[bb][i]);
            }
            int base = ((bpair*2+bb) * FEAT_ + F0 + fl) * WW + w0;
            *(float4*)&g_hstate[(y & 1) ^ 1][base] = make_float4(hn[0], hn[1], hn[2], hn[3]);
            *(float4*)&g_outh[(((bpair*2+bb) * FEAT_ + F0 + fl) * HH + y) * WW + w0] =
                make_float4(tf32r(hn[0]), tf32r(hn[1]), tf32r(hn[2]), tf32r(hn[3]));
        }

        if (y < HH - 1) {
#pragma unroll
            for (int bb = 0; bb < 2; bb++)
#pragma unroll
                for (int g = 0; g < 4; g++)
                    hv[bb][g] = *(const float4*)&g_h[(((long)(bpair*2+bb) * CG + g*FEAT_ + F0 + fl) * HH + (y+1)) * WW + w0];
            __syncthreads();
            if (tid == 0) {
                __threadfence();
                atomicAdd(bar, 1u);
                unsigned target = 24u * (unsigned)(y + 1);
                while (atomicAdd(bar, 0u) < target) __nanosleep(32);
                __threadfence();
            }
            __syncthreads();
        }
    }
}

// ---------------------------------------------------------------------------
// skip via mma.sync tf32: out = x + b_skip + Wskip @ outh, mask -> K bound.
// Per CTA: M=128 co, N=128 (2 rows x 64 w), K = 64*(co_block+1).
// ---------------------------------------------------------------------------
#define SKIP_SMEM ((4608 + 4608) * 4)

__global__ void __launch_bounds__(256, 2) skip_mma_kernel(const float* __restrict__ x,
                                                          const float* __restrict__ b_skip,
                                                          float* __restrict__ out) {
    extern __shared__ float sm[];
    float* wa = sm;               // [oc][kk] stride 36
    float* os = sm + 4608;        // [yr][k][w] stride 72

    int tid = threadIdx.x, lane = tid & 31, wid = tid >> 5;
    int OC0 = blockIdx.x * 128;
    int b = blockIdx.y >> 5, y0 = (blockIdx.y & 31) * 2;
    int nchunks = (OC0 >> 6) + 2;     // 2 / 4 / 6

    float d[16][4];
#pragma unroll
    for (int nt = 0; nt < 16; nt++)
#pragma unroll
        for (int i = 0; i < 4; i++) d[nt][i] = 0.f;

    const float* ob = g_outh + (long)b * FEAT_ * HH * WW;
    int m0 = wid * 16;

    for (int c = 0; c < nchunks; c++) {
        int k0 = c * 32;
        __syncthreads();
#pragma unroll
        for (int i = tid; i < 1024; i += 256) {
            int oc = i >> 3, kk = i & 7;
            *(float4*)&wa[oc * 36 + kk * 4] =
                *(const float4*)&g_wskt2[(OC0 + oc) * FEAT_ + k0 + kk * 4];
        }
#pragma unroll
        for (int i = tid; i < 1024; i += 256) {
            int yr = i >> 9, r = i & 511, k = r >> 4, w4 = r & 15;
            *(float4*)&os[yr * 2304 + k * 72 + w4 * 4] =
                *(const float4*)&ob[((long)(k0 + k) * HH + y0 + yr) * WW + w4 * 4];
        }
        __syncthreads();
#pragma unroll
        for (int k8 = 0; k8 < 4; k8++) {
            const float* wp = wa + (m0 + (lane >> 2)) * 36 + k8 * 8 + (lane & 3);
            uint32_t a0 = F2U(wp[0]);
            uint32_t a1 = F2U(wp[8 * 36]);
            uint32_t a2 = F2U(wp[4]);
            uint32_t a3 = F2U(wp[8 * 36 + 4]);
#pragma unroll
            for (int nt = 0; nt < 16; nt++) {
                const float* hb = os + (nt >> 3) * 2304 + (k8 * 8 + (lane & 3)) * 72
                                  + (nt & 7) * 8 + (lane >> 2);
                mma8(d[nt], a0, a1, a2, a3, F2U(hb[0]), F2U(hb[4 * 72]));
            }
        }
    }

    int ocl = OC0 + wid * 16 + (lane >> 2);
    float bs0 = b_skip[ocl], bs1 = b_skip[ocl + 8];
#pragma unroll
    for (int nt = 0; nt < 16; nt++) {
        int y = y0 + (nt >> 3);
        int w = (nt & 7) * 8 + (lane & 3) * 2;
        long off = ((long)(b * CIN_ + ocl) * HH + y) * WW + w;
        float2 xv = *(const float2*)&x[off];
        *(float2*)&out[off] = make_float2(d[nt][0] + xv.x + bs0, d[nt][1] + xv.y + bs0);
        long off2 = off + (long)8 * HH * WW;
        float2 xv2 = *(const float2*)&x[off2];
        *(float2*)&out[off2] = make_float2(d[nt][2] + xv2.x + bs1, d[nt][3] + xv2.y + bs1);
    }
}

// ---------------------------------------------------------------------------
extern "C" void kernel_launch(void* const* d_in, const int* in_sizes, int n_in,
                              void* d_out, int out_size) {
    const float* x      = (const float*)d_in[0];
    const float* w_i2s  = (const float*)d_in[1];
    const float* w_s2s  = (const float*)d_in[2];
    const float* w_skip = (const float*)d_in[3];
    const float* b_skip = (const float*)d_in[4];
    float* out = (float*)d_out;

    cudaFuncSetAttribute(i2s_mma_kernel, cudaFuncAttributeMaxDynamicSharedMemorySize, I2S_SMEM);
    cudaFuncSetAttribute(lstm_scan_mma, cudaFuncAttributeMaxDynamicSharedMemorySize, SCAN_SMEM);
    cudaFuncSetAttribute(skip_mma_kernel, cudaFuncAttributeMaxDynamicSharedMemorySize, SKIP_SMEM);

    prep_kernel<<<(FEAT_ * 3 * CG + 255) / 256, 256>>>(w_i2s, w_s2s, w_skip);
    init_kernel<<<(NB * FEAT_ * WW + 255) / 256, 256>>>();
    i2s_mma_kernel<<<dim3(6, 512), 256, I2S_SMEM>>>(x);
    lstm_scan_mma<<<dim3(24, 8), 128, SCAN_SMEM>>>();
    skip_mma_kernel<<<dim3(3, 512), 256, SKIP_SMEM>>>(x, b_skip, out);
}

// round 6
// speedup vs baseline: 3.5357x; 1.1394x over previous
#include <cuda_runtime.h>
#include <cuda_bf16.h>
#include <math.h>
#include <stdint.h>

#define NB    16
#define CIN_  384
#define CG    768
#define FEAT_ 192
#define HH    64
#define WW    64

// Scratch (device globals; no allocations allowed)
__device__ float g_h[NB * CG * HH * WW];            // shuffled gate inputs (b, c', y, w)
__device__ float g_Wa[2][CG * CIN_];                // i2s weights [tap][oc'][ic], tf32-rounded
__device__ __nv_bfloat16 g_w1rb[24 * 3 * 32 * 192]; // s2s weights [ftile][t][ocr][kf], bf16
__device__ float g_wskt2[CIN_ * FEAT_];             // skip weights [co][ci], tf32-rounded
__device__ float g_hstate[2][NB * FEAT_ * WW];      // LSTM hidden, double buffered
__device__ float g_outh[NB * FEAT_ * HH * WW];      // scan outputs (tf32-rounded)
__device__ unsigned g_rowbar[NB * 32];              // per-bpair row barriers

__device__ __forceinline__ float sigf(float v) { return 1.0f / (1.0f + __expf(-v)); }
__device__ __forceinline__ float tanhfast(float x) {
    float y; asm("tanh.approx.f32 %0, %1;" : "=f"(y) : "f"(x)); return y;
}
__device__ __forceinline__ float tf32r(float x) {
    uint32_t u; asm("cvt.rna.tf32.f32 %0, %1;" : "=r"(u) : "f"(x));
    return __uint_as_float(u);
}
__device__ __forceinline__ uint32_t smem_u32(const void* p) {
    uint32_t a;
    asm("{ .reg .u64 t; cvta.to.shared.u64 t, %1; cvt.u32.u64 %0, t; }" : "=r"(a) : "l"(p));
    return a;
}
// pack two f32 -> bf16x2 (lo = first arg, hi = second)
__device__ __forceinline__ uint32_t pk2(float lo, float hi) {
    uint32_t r; asm("cvt.rn.bf16x2.f32 %0, %1, %2;" : "=r"(r) : "f"(hi), "f"(lo));
    return r;
}
#define F2U(x) __float_as_uint(x)
#define CP_ASYNC16(dst, src) \
    asm volatile("cp.async.cg.shared.global [%0], [%1], 16;" :: "r"(dst), "l"(src) : "memory")
#define CP_COMMIT() asm volatile("cp.async.commit_group;" ::: "memory")
#define CP_WAIT1()  asm volatile("cp.async.wait_group 1;" ::: "memory")
#define CP_WAIT0()  asm volatile("cp.async.wait_group 0;" ::: "memory")

// tf32 m16n8k8 (i2s / skip)
__device__ __forceinline__ void mma8(float* d, uint32_t a0, uint32_t a1, uint32_t a2, uint32_t a3,
                                     uint32_t b0, uint32_t b1) {
    asm volatile("mma.sync.aligned.m16n8k8.row.col.f32.tf32.tf32.f32 "
                 "{%0,%1,%2,%3}, {%4,%5,%6,%7}, {%8,%9}, {%0,%1,%2,%3};"
                 : "+f"(d[0]), "+f"(d[1]), "+f"(d[2]), "+f"(d[3])
                 : "r"(a0), "r"(a1), "r"(a2), "r"(a3), "r"(b0), "r"(b1));
}
// bf16 m16n8k16 (scan)
__device__ __forceinline__ void mma16(float* d, uint32_t a0, uint32_t a1, uint32_t a2, uint32_t a3,
                                      uint32_t b0, uint32_t b1) {
    asm volatile("mma.sync.aligned.m16n8k16.row.col.f32.bf16.bf16.f32 "
                 "{%0,%1,%2,%3}, {%4,%5,%6,%7}, {%8,%9}, {%0,%1,%2,%3};"
                 : "+f"(d[0]), "+f"(d[1]), "+f"(d[2]), "+f"(d[3])
                 : "r"(a0), "r"(a1), "r"(a2), "r"(a3), "r"(b0), "r"(b1));
}
#define LDSM_X4(r0, r1, r2, r3, a) \
    asm volatile("ldmatrix.sync.aligned.m8n8.x4.shared.b16 {%0,%1,%2,%3}, [%4];" \
                 : "=r"(r0), "=r"(r1), "=r"(r2), "=r"(r3) : "r"(a))
#define LDSM_X2T(r0, r1, a) \
    asm volatile("ldmatrix.sync.aligned.m8n8.x2.trans.shared.b16 {%0,%1}, [%2];" \
                 : "=r"(r0), "=r"(r1) : "r"(a))

// ---------------------------------------------------------------------------
// Weight prep
// ---------------------------------------------------------------------------
__global__ void prep_kernel(const float* __restrict__ w_i2s,
                            const float* __restrict__ w_s2s,
                            const float* __restrict__ w_skip) {
    int idx = blockIdx.x * blockDim.x + threadIdx.x;
    if (idx < CG * CIN_) {
        int ocp = idx / CIN_, ic = idx % CIN_;
        int q = ocp / 192, p = (ocp % 192) / 64, fl = ocp % 64;
        int c = p * 256 + q * 64 + fl;
        const float* wb = w_i2s + ((long)c * CIN_ + ic) * 3;
        g_Wa[0][idx] = tf32r(wb[0]);
        g_Wa[1][idx] = (p >= (ic / 128)) ? tf32r(wb[1]) : 0.f;
    }
    if (idx < 24 * 3 * 32 * 192) {                   // bf16 s2s: [ftile][t][ocr][kf]
        int ftile = idx / 18432;
        int r2 = idx % 18432;
        int t = r2 / 6144;
        int r3 = r2 % 6144;
        int ocr = r3 / 192, kf = r3 % 192;
        int gate = ocr >> 3, j = ocr & 7;
        int oc = gate * FEAT_ + ftile * 8 + j;
        g_w1rb[idx] = __float2bfloat16(w_s2s[((long)oc * FEAT_ + kf) * 3 + t]);
    }
    if (idx < CIN_ * FEAT_) {
        g_wskt2[idx] = tf32r(w_skip[idx]);
    }
}

__global__ void init_kernel() {
    int i = blockIdx.x * blockDim.x + threadIdx.x;
    if (i < NB * FEAT_ * WW) g_hstate[0][i] = 0.f;
    if (i < NB * 32) g_rowbar[i] = 0u;
}

// ---------------------------------------------------------------------------
// i2s via mma.sync tf32 (unchanged from R5)
// ---------------------------------------------------------------------------
#define I2S_SMEM 55296

__global__ void __launch_bounds__(256, 2) i2s_mma_kernel(const float* __restrict__ x) {
    extern __shared__ float sm[];
    float* wa = sm;               // [t][oc][kk] stride 36
    float* xs = sm + 9216;        // [yr][k][i] stride 72, i=w+1 (halo at 0)

    int tid = threadIdx.x, lane = tid & 31, wid = tid >> 5;
    int OC0 = blockIdx.x * 128;
    int b = blockIdx.y >> 5, y0 = (blockIdx.y & 31) * 2;

    if (tid < 64) xs[(tid >> 5) * 2304 + (tid & 31) * 72] = 0.f;

    float d[16][4];
#pragma unroll
    for (int nt = 0; nt < 16; nt++)
#pragma unroll
        for (int i = 0; i < 4; i++) d[nt][i] = 0.f;

    const float* xb = x + (long)b * CIN_ * HH * WW;
    int m0 = wid * 16;

    for (int c = 0; c < 12; c++) {
        int k0 = c * 32;
        __syncthreads();
#pragma unroll
        for (int i = tid; i < 2048; i += 256) {
            int t = i >> 10, r = i & 1023, oc = r >> 3, kk = r & 7;
            float4 v = *(const float4*)&g_Wa[t][(OC0 + oc) * CIN_ + k0 + kk * 4];
            *(float4*)&wa[t * 4608 + oc * 36 + kk * 4] = v;
        }
#pragma unroll
        for (int i = tid; i < 4096; i += 256) {
            int yr = i >> 11, r = i & 2047, k = r >> 6, w = r & 63;
            float v = xb[((long)(k0 + k) * HH + y0 + yr) * WW + w];
            xs[yr * 2304 + k * 72 + w + 1] = tf32r(v);
        }
        __syncthreads();
#pragma unroll
        for (int k8 = 0; k8 < 4; k8++) {
#pragma unroll
            for (int t = 0; t < 2; t++) {
                const float* wp = wa + t * 4608 + (m0 + (lane >> 2)) * 36 + k8 * 8 + (lane & 3);
                uint32_t a0 = F2U(wp[0]);
                uint32_t a1 = F2U(wp[8 * 36]);
                uint32_t a2 = F2U(wp[4]);
                uint32_t a3 = F2U(wp[8 * 36 + 4]);
#pragma unroll
                for (int nt = 0; nt < 16; nt++) {
                    const float* hb = xs + (nt >> 3) * 2304 + (k8 * 8 + (lane & 3)) * 72
                                      + (nt & 7) * 8 + (lane >> 2) + t;
                    mma8(d[nt], a0, a1, a2, a3, F2U(hb[0]), F2U(hb[4 * 72]));
                }
            }
        }
    }

    int ocl = OC0 + wid * 16 + (lane >> 2);
#pragma unroll
    for (int nt = 0; nt < 16; nt++) {
        int y = y0 + (nt >> 3);
        int w = (nt & 7) * 8 + (lane & 3) * 2;
        float* p0 = &g_h[(((long)b * CG + ocl) * HH + y) * WW + w];
        *(float2*)p0 = make_float2(d[nt][0], d[nt][1]);
        *(float2*)(p0 + (long)8 * HH * WW) = make_float2(d[nt][2], d[nt][3]);
    }
}

// ---------------------------------------------------------------------------
// Persistent LSTM scan: bf16 m16n8k16 + ldmatrix.
// grid (24, 8) = 192 CTAs, 256 thr, 100.5KB smem -> 2 CTA/SM co-resident.
// smem: wstb bf16 [3t][32m][200] | hpf f32 [2buf][2bb][32kf][72] (cp.async dst,
//       data cols 4..67, halos 3/68) | hpt bf16 [3t][2bb][32kf][72] (tap-shifted)
// sbuf (f32 [2][32][68]) overlays hpf.
// ---------------------------------------------------------------------------
#define SCAN_SMEM (38400 + 36864 + 27648)

__global__ void __launch_bounds__(256, 2) lstm_scan_mma() {
    extern __shared__ char smc[];
    uint32_t* wstb_u = (uint32_t*)smc;                       // 9600 uints (halves/2)
    float* hpf = (float*)(smc + 38400);                      // 9216 floats
    uint32_t* hpt_u = (uint32_t*)(smc + 38400 + 36864);      // 13824 uints
    float* sbuf = hpf;                                       // overlay
    uint32_t wstb32 = smem_u32(wstb_u);
    uint32_t hpt32 = smem_u32(hpt_u);

    int tid = threadIdx.x, lane = tid & 31, wid = tid >> 5;
    int ftile = blockIdx.x, bpair = blockIdx.y;
    int F0 = ftile * 8;
    // mma warp tiling: m0 in {0,16}, bb in {0,1}, n0 in {0,32}
    int m0 = (wid & 1) * 16;
    int wbb = wid >> 2;
    int n0 = ((wid >> 1) & 1) * 32;
    // pointwise mapping
    int pbb = tid >> 7, fl = (tid >> 4) & 7, w0 = (tid & 15) * 4;
    // pass-B mapping
    int sbb = tid >> 7, skf = (tid >> 2) & 31, sq = tid & 3;

    // load weights (bf16) once: 9216 uints, src contiguous, dst stride 100 uints/row
    {
        const uint32_t* src = (const uint32_t*)&g_w1rb[(long)ftile * 18432];
#pragma unroll
        for (int j = tid; j < 9216; j += 256)
            wstb_u[(j / 96) * 100 + (j % 96)] = src[j];
    }
    // hpf halos (cols 3 and 68) for both buffers: 256 slots
    {
        int bf = tid >> 7, bb = (tid >> 6) & 1, kf = (tid >> 1) & 31, hc = (tid & 1) ? 68 : 3;
        hpf[((bf * 2 + bb) * 32 + kf) * 72 + hc] = 0.f;
    }

    float creg[4] = {0.f, 0.f, 0.f, 0.f};
    float4 hv[4];
    {
        int b = bpair * 2 + pbb;
#pragma unroll
        for (int g = 0; g < 4; g++)
            hv[g] = *(const float4*)&g_h[(((long)(b * CG + g * FEAT_ + F0 + fl)) * HH + 0) * WW + w0];
    }
    __syncthreads();

    unsigned* bar = &g_rowbar[bpair * 32];

    // ldmatrix lane base offsets
    int a_row = (m0 + (lane & 15)) * 200 + ((lane >> 4) << 3);   // halves
    int b_row = (lane & 15);                                     // kf within tile

    for (int y = 0; y < HH; y++) {
        const float* hsr = g_hstate[y & 1];

        auto issue_chunk = [&](int ch, int buf) {
            int f0k = ch * 32;
#pragma unroll
            for (int j = 0; j < 4; j++) {
                int i = tid + j * 256;
                int bb = i >> 9, r = i & 511, kf = r >> 4, w4 = r & 15;
                uint32_t da = smem_u32(&hpf[((buf * 2 + bb) * 32 + kf) * 72 + 4 + w4 * 4]);
                const float* sa = hsr + ((bpair * 2 + bb) * FEAT_ + f0k + kf) * WW + w4 * 4;
                CP_ASYNC16(da, sa);
            }
        };

        float d[4][4];
#pragma unroll
        for (int nt = 0; nt < 4; nt++)
#pragma unroll
            for (int i = 0; i < 4; i++) d[nt][i] = 0.f;

        issue_chunk(0, 0);
        CP_COMMIT();

        for (int ch = 0; ch < 6; ch++) {
            if (ch < 5) { issue_chunk(ch + 1, (ch + 1) & 1); CP_COMMIT(); CP_WAIT1(); }
            else CP_WAIT0();
            __syncthreads();   // hpf[ch] ready; hpt free (prev mma done)

            // pass B: hpf -> 3 tap-shifted bf16 copies in hpt
            {
                const float* base = &hpf[(((ch & 1) * 2 + sbb) * 32 + skf) * 72 + 3 + sq * 16];
                float lm = base[0];
                float m[16];
#pragma unroll
                for (int j = 0; j < 4; j++) {
                    float4 v = *(const float4*)&base[1 + j * 4];
                    m[j*4] = v.x; m[j*4+1] = v.y; m[j*4+2] = v.z; m[j*4+3] = v.w;
                }
                float rp = base[17];
                uint32_t u0[8], u1[8], u2[8];
                u0[0] = pk2(lm, m[0]);
#pragma unroll
                for (int i = 1; i < 8; i++) u0[i] = pk2(m[2*i-1], m[2*i]);
#pragma unroll
                for (int i = 0; i < 8; i++) u1[i] = pk2(m[2*i], m[2*i+1]);
#pragma unroll
                for (int i = 0; i < 7; i++) u2[i] = pk2(m[2*i+1], m[2*i+2]);
                u2[7] = pk2(m[15], rp);
                int dbase = (sbb * 32 + skf) * 36 + sq * 8;      // uint idx within one tap
#pragma unroll
                for (int t = 0; t < 3; t++) {
                    uint32_t* up = (t == 0) ? u0 : (t == 1) ? u1 : u2;
                    uint32_t* dp = hpt_u + t * 2304 + dbase;
                    *(uint4*)dp = make_uint4(up[0], up[1], up[2], up[3]);
                    *(uint4*)(dp + 4) = make_uint4(up[4], up[5], up[6], up[7]);
                }
            }
            __syncthreads();   // hpt ready

            int kbase = ch * 32;
#pragma unroll
            for (int t = 0; t < 3; t++) {
#pragma unroll
                for (int kk = 0; kk < 2; kk++) {
                    uint32_t a0, a1, a2, a3;
                    uint32_t aaddr = wstb32 + 2 * (t * 6400 + a_row + kbase + kk * 16);
                    LDSM_X4(a0, a1, a2, a3, aaddr);
#pragma unroll
                    for (int nt = 0; nt < 4; nt++) {
                        uint32_t b0, b1;
                        uint32_t baddr = hpt32 + 2 * (((t * 2 + wbb) * 32 + kk * 16 + b_row) * 72
                                                      + n0 + nt * 8);
                        LDSM_X2T(b0, b1, baddr);
                        mma16(d[nt], a0, a1, a2, a3, b0, b1);
                    }
                }
            }
            __syncthreads();   // mma done before next pass B overwrites hpt
        }

        // epilogue: write s to sbuf (overlays hpf; all hpf reads complete)
#pragma unroll
        for (int nt = 0; nt < 4; nt++) {
            int r = m0 + (lane >> 2);
            int cc = n0 + nt * 8 + (lane & 3) * 2;
            *(float2*)&sbuf[wbb * 2176 + r * 68 + cc] = make_float2(d[nt][0], d[nt][1]);
            *(float2*)&sbuf[wbb * 2176 + (r + 8) * 68 + cc] = make_float2(d[nt][2], d[nt][3]);
        }
        __syncthreads();

        // pointwise gate update
        {
            float* sb = sbuf + pbb * 2176;
            float4 ov = *(const float4*)&sb[fl * 68 + w0];
            float4 fv = *(const float4*)&sb[(8 + fl) * 68 + w0];
            float4 iv = *(const float4*)&sb[(16 + fl) * 68 + w0];
            float4 gv = *(const float4*)&sb[(24 + fl) * 68 + w0];
            float so[4] = {sigf(ov.x + hv[0].x), sigf(ov.y + hv[0].y),
                           sigf(ov.z + hv[0].z), sigf(ov.w + hv[0].w)};
            float sf[4] = {sigf(fv.x + hv[1].x), sigf(fv.y + hv[1].y),
                           sigf(fv.z + hv[1].z), sigf(fv.w + hv[1].w)};
            float si[4] = {sigf(iv.x + hv[2].x), sigf(iv.y + hv[2].y),
                           sigf(iv.z + hv[2].z), sigf(iv.w + hv[2].w)};
            float sg[4] = {sigf(gv.x + hv[3].x), sigf(gv.y + hv[3].y),
                           sigf(gv.z + hv[3].z), sigf(gv.w + hv[3].w)};
            float hn[4];
#pragma unroll
            for (int i = 0; i < 4; i++) {
                creg[i] = sf[i] * creg[i] + si[i] * sg[i];
                hn[i] = so[i] * tanhfast(creg[i]);
            }
            int b = bpair * 2 + pbb;
            int base = (b * FEAT_ + F0 + fl) * WW + w0;
            *(float4*)&g_hstate[(y & 1) ^ 1][base] = make_float4(hn[0], hn[1], hn[2], hn[3]);
            *(float4*)&g_outh[((b * FEAT_ + F0 + fl) * HH + y) * WW + w0] =
                make_float4(tf32r(hn[0]), tf32r(hn[1]), tf32r(hn[2]), tf32r(hn[3]));
        }

        if (y < HH - 1) {
            // prefetch next row's gate inputs
            int b = bpair * 2 + pbb;
#pragma unroll
            for (int g = 0; g < 4; g++)
                hv[g] = *(const float4*)&g_h[(((long)(b * CG + g * FEAT_ + F0 + fl)) * HH + (y + 1)) * WW + w0];
            __syncthreads();   // all hstate stores issued
            if (tid == 0) {
                asm volatile("red.release.gpu.global.add.u32 [%0], %1;" :: "l"(bar), "r"(1u) : "memory");
                unsigned target = 24u * (unsigned)(y + 1);
                unsigned v;
                do {
                    asm volatile("ld.acquire.gpu.global.u32 %0, [%1];" : "=r"(v) : "l"(bar) : "memory");
                } while (v < target);
            }
            __syncthreads();
        }
    }
}

// ---------------------------------------------------------------------------
// skip via mma.sync tf32 (unchanged from R5)
// ---------------------------------------------------------------------------
#define SKIP_SMEM ((4608 + 4608) * 4)

__global__ void __launch_bounds__(256, 2) skip_mma_kernel(const float* __restrict__ x,
                                                          const float* __restrict__ b_skip,
                                                          float* __restrict__ out) {
    extern __shared__ float sm[];
    float* wa = sm;
    float* os = sm + 4608;

    int tid = threadIdx.x, lane = tid & 31, wid = tid >> 5;
    int OC0 = blockIdx.x * 128;
    int b = blockIdx.y >> 5, y0 = (blockIdx.y & 31) * 2;
    int nchunks = (OC0 >> 6) + 2;

    float d[16][4];
#pragma unroll
    for (int nt = 0; nt < 16; nt++)
#pragma unroll
        for (int i = 0; i < 4; i++) d[nt][i] = 0.f;

    const float* ob = g_outh + (long)b * FEAT_ * HH * WW;
    int m0 = wid * 16;

    for (int c = 0; c < nchunks; c++) {
        int k0 = c * 32;
        __syncthreads();
#pragma unroll
        for (int i = tid; i < 1024; i += 256) {
            int oc = i >> 3, kk = i & 7;
            *(float4*)&wa[oc * 36 + kk * 4] =
                *(const float4*)&g_wskt2[(OC0 + oc) * FEAT_ + k0 + kk * 4];
        }
#pragma unroll
        for (int i = tid; i < 1024; i += 256) {
            int yr = i >> 9, r = i & 511, k = r >> 4, w4 = r & 15;
            *(float4*)&os[yr * 2304 + k * 72 + w4 * 4] =
                *(const float4*)&ob[((long)(k0 + k) * HH + y0 + yr) * WW + w4 * 4];
        }
        __syncthreads();
#pragma unroll
        for (int k8 = 0; k8 < 4; k8++) {
            const float* wp = wa + (m0 + (lane >> 2)) * 36 + k8 * 8 + (lane & 3);
            uint32_t a0 = F2U(wp[0]);
            uint32_t a1 = F2U(wp[8 * 36]);
            uint32_t a2 = F2U(wp[4]);
            uint32_t a3 = F2U(wp[8 * 36 + 4]);
#pragma unroll
            for (int nt = 0; nt < 16; nt++) {
                const float* hb = os + (nt >> 3) * 2304 + (k8 * 8 + (lane & 3)) * 72
                                  + (nt & 7) * 8 + (lane >> 2);
                mma8(d[nt], a0, a1, a2, a3, F2U(hb[0]), F2U(hb[4 * 72]));
            }
        }
    }

    int ocl = OC0 + wid * 16 + (lane >> 2);
    float bs0 = b_skip[ocl], bs1 = b_skip[ocl + 8];
#pragma unroll
    for (int nt = 0; nt < 16; nt++) {
        int y = y0 + (nt >> 3);
        int w = (nt & 7) * 8 + (lane & 3) * 2;
        long off = ((long)(b * CIN_ + ocl) * HH + y) * WW + w;
        float2 xv = *(const float2*)&x[off];
        *(float2*)&out[off] = make_float2(d[nt][0] + xv.x + bs0, d[nt][1] + xv.y + bs0);
        long off2 = off + (long)8 * HH * WW;
        float2 xv2 = *(const float2*)&x[off2];
        *(float2*)&out[off2] = make_float2(d[nt][2] + xv2.x + bs1, d[nt][3] + xv2.y + bs1);
    }
}

// ---------------------------------------------------------------------------
extern "C" void kernel_launch(void* const* d_in, const int* in_sizes, int n_in,
                              void* d_out, int out_size) {
    const float* x      = (const float*)d_in[0];
    const float* w_i2s  = (const float*)d_in[1];
    const float* w_s2s  = (const float*)d_in[2];
    const float* w_skip = (const float*)d_in[3];
    const float* b_skip = (const float*)d_in[4];
    float* out = (float*)d_out;

    cudaFuncSetAttribute(i2s_mma_kernel, cudaFuncAttributeMaxDynamicSharedMemorySize, I2S_SMEM);
    cudaFuncSetAttribute(lstm_scan_mma, cudaFuncAttributeMaxDynamicSharedMemorySize, SCAN_SMEM);
    cudaFuncSetAttribute(skip_mma_kernel, cudaFuncAttributeMaxDynamicSharedMemorySize, SKIP_SMEM);

    prep_kernel<<<(24 * 3 * 32 * 192 + 255) / 256, 256>>>(w_i2s, w_s2s, w_skip);
    init_kernel<<<(NB * FEAT_ * WW + 255) / 256, 256>>>();
    i2s_mma_kernel<<<dim3(6, 512), 256, I2S_SMEM>>>(x);
    lstm_scan_mma<<<dim3(24, 8), 256, SCAN_SMEM>>>();
    skip_mma_kernel<<<dim3(3, 512), 256, SKIP_SMEM>>>(x, b_skip, out);
}

// round 7
// speedup vs baseline: 4.1652x; 1.1781x over previous
#include <cuda_runtime.h>
#include <cuda_bf16.h>
#include <math.h>
#include <stdint.h>

#define NB    16
#define CIN_  384
#define CG    768
#define FEAT_ 192
#define HH    64
#define WW    64
#define HSZ   (NB * FEAT_ * WW)

// Scratch (device globals; no allocations allowed)
__device__ float g_h[NB * CG * HH * WW];            // shuffled gate inputs (b, c', y, w)
__device__ float g_Wa[2][CG * CIN_];                // i2s weights [tap][oc'][ic], tf32-rounded
__device__ __nv_bfloat16 g_w1rb[24 * 3 * 32 * 192]; // s2s weights [ftile][t][ocr][kf], bf16
__device__ float g_wskt2[CIN_ * FEAT_];             // skip weights [co][ci], tf32-rounded
__device__ __nv_bfloat16 g_hsh[2][3][HSZ];          // hidden, tap-shifted bf16, double buffered
__device__ float g_outh[NB * FEAT_ * HH * WW];      // scan outputs (tf32-rounded)
__device__ unsigned g_rowbar[NB * 32];              // per-bpair row barriers

__device__ __forceinline__ float sigf(float v) { return 1.0f / (1.0f + __expf(-v)); }
__device__ __forceinline__ float tanhfast(float x) {
    float y; asm("tanh.approx.f32 %0, %1;" : "=f"(y) : "f"(x)); return y;
}
__device__ __forceinline__ float tf32r(float x) {
    uint32_t u; asm("cvt.rna.tf32.f32 %0, %1;" : "=r"(u) : "f"(x));
    return __uint_as_float(u);
}
__device__ __forceinline__ uint32_t smem_u32(const void* p) {
    uint32_t a;
    asm("{ .reg .u64 t; cvta.to.shared.u64 t, %1; cvt.u32.u64 %0, t; }" : "=r"(a) : "l"(p));
    return a;
}
// pack two f32 -> bf16x2 (lo = first arg, hi = second)
__device__ __forceinline__ uint32_t pk2(float lo, float hi) {
    uint32_t r; asm("cvt.rn.bf16x2.f32 %0, %1, %2;" : "=r"(r) : "f"(hi), "f"(lo));
    return r;
}
#define F2U(x) __float_as_uint(x)
#define CP_ASYNC16(dst, src) \
    asm volatile("cp.async.cg.shared.global [%0], [%1], 16;" :: "r"(dst), "l"(src) : "memory")
#define CP_COMMIT() asm volatile("cp.async.commit_group;" ::: "memory")
#define CP_WAIT1()  asm volatile("cp.async.wait_group 1;" ::: "memory")
#define CP_WAIT0()  asm volatile("cp.async.wait_group 0;" ::: "memory")

// tf32 m16n8k8 (i2s / skip)
__device__ __forceinline__ void mma8(float* d, uint32_t a0, uint32_t a1, uint32_t a2, uint32_t a3,
                                     uint32_t b0, uint32_t b1) {
    asm volatile("mma.sync.aligned.m16n8k8.row.col.f32.tf32.tf32.f32 "
                 "{%0,%1,%2,%3}, {%4,%5,%6,%7}, {%8,%9}, {%0,%1,%2,%3};"
                 : "+f"(d[0]), "+f"(d[1]), "+f"(d[2]), "+f"(d[3])
                 : "r"(a0), "r"(a1), "r"(a2), "r"(a3), "r"(b0), "r"(b1));
}
// bf16 m16n8k16 (scan)
__device__ __forceinline__ void mma16(float* d, uint32_t a0, uint32_t a1, uint32_t a2, uint32_t a3,
                                      uint32_t b0, uint32_t b1) {
    asm volatile("mma.sync.aligned.m16n8k16.row.col.f32.bf16.bf16.f32 "
                 "{%0,%1,%2,%3}, {%4,%5,%6,%7}, {%8,%9}, {%0,%1,%2,%3};"
                 : "+f"(d[0]), "+f"(d[1]), "+f"(d[2]), "+f"(d[3])
                 : "r"(a0), "r"(a1), "r"(a2), "r"(a3), "r"(b0), "r"(b1));
}
#define LDSM_X4(r0, r1, r2, r3, a) \
    asm volatile("ldmatrix.sync.aligned.m8n8.x4.shared.b16 {%0,%1,%2,%3}, [%4];" \
                 : "=r"(r0), "=r"(r1), "=r"(r2), "=r"(r3) : "r"(a))
#define LDSM_X2T(r0, r1, a) \
    asm volatile("ldmatrix.sync.aligned.m8n8.x2.trans.shared.b16 {%0,%1}, [%2];" \
                 : "=r"(r0), "=r"(r1) : "r"(a))

// ---------------------------------------------------------------------------
// Weight prep
// ---------------------------------------------------------------------------
__global__ void prep_kernel(const float* __restrict__ w_i2s,
                            const float* __restrict__ w_s2s,
                            const float* __restrict__ w_skip) {
    int idx = blockIdx.x * blockDim.x + threadIdx.x;
    if (idx < CG * CIN_) {
        int ocp = idx / CIN_, ic = idx % CIN_;
        int q = ocp / 192, p = (ocp % 192) / 64, fl = ocp % 64;
        int c = p * 256 + q * 64 + fl;
        const float* wb = w_i2s + ((long)c * CIN_ + ic) * 3;
        g_Wa[0][idx] = tf32r(wb[0]);
        g_Wa[1][idx] = (p >= (ic / 128)) ? tf32r(wb[1]) : 0.f;
    }
    if (idx < 24 * 3 * 32 * 192) {                   // bf16 s2s: [ftile][t][ocr][kf]
        int ftile = idx / 18432;
        int r2 = idx % 18432;
        int t = r2 / 6144;
        int r3 = r2 % 6144;
        int ocr = r3 / 192, kf = r3 % 192;
        int gate = ocr >> 3, j = ocr & 7;
        int oc = gate * FEAT_ + ftile * 8 + j;
        g_w1rb[idx] = __float2bfloat16(w_s2s[((long)oc * FEAT_ + kf) * 3 + t]);
    }
    if (idx < CIN_ * FEAT_) {
        g_wskt2[idx] = tf32r(w_skip[idx]);
    }
}

__global__ void init_kernel() {
    int i = blockIdx.x * blockDim.x + threadIdx.x;
    if (i < 3 * HSZ / 2) ((uint32_t*)&g_hsh[0][0][0])[i] = 0u;   // zero parity-0 state
    if (i < NB * 32) g_rowbar[i] = 0u;
}

// ---------------------------------------------------------------------------
// i2s via mma.sync tf32 (unchanged)
// ---------------------------------------------------------------------------
#define I2S_SMEM 55296

__global__ void __launch_bounds__(256, 2) i2s_mma_kernel(const float* __restrict__ x) {
    extern __shared__ float sm[];
    float* wa = sm;               // [t][oc][kk] stride 36
    float* xs = sm + 9216;        // [yr][k][i] stride 72, i=w+1 (halo at 0)

    int tid = threadIdx.x, lane = tid & 31, wid = tid >> 5;
    int OC0 = blockIdx.x * 128;
    int b = blockIdx.y >> 5, y0 = (blockIdx.y & 31) * 2;

    if (tid < 64) xs[(tid >> 5) * 2304 + (tid & 31) * 72] = 0.f;

    float d[16][4];
#pragma unroll
    for (int nt = 0; nt < 16; nt++)
#pragma unroll
        for (int i = 0; i < 4; i++) d[nt][i] = 0.f;

    const float* xb = x + (long)b * CIN_ * HH * WW;
    int m0 = wid * 16;

    for (int c = 0; c < 12; c++) {
        int k0 = c * 32;
        __syncthreads();
#pragma unroll
        for (int i = tid; i < 2048; i += 256) {
            int t = i >> 10, r = i & 1023, oc = r >> 3, kk = r & 7;
            float4 v = *(const float4*)&g_Wa[t][(OC0 + oc) * CIN_ + k0 + kk * 4];
            *(float4*)&wa[t * 4608 + oc * 36 + kk * 4] = v;
        }
#pragma unroll
        for (int i = tid; i < 4096; i += 256) {
            int yr = i >> 11, r = i & 2047, k = r >> 6, w = r & 63;
            float v = xb[((long)(k0 + k) * HH + y0 + yr) * WW + w];
            xs[yr * 2304 + k * 72 + w + 1] = tf32r(v);
        }
        __syncthreads();
#pragma unroll
        for (int k8 = 0; k8 < 4; k8++) {
#pragma unroll
            for (int t = 0; t < 2; t++) {
                const float* wp = wa + t * 4608 + (m0 + (lane >> 2)) * 36 + k8 * 8 + (lane & 3);
                uint32_t a0 = F2U(wp[0]);
                uint32_t a1 = F2U(wp[8 * 36]);
                uint32_t a2 = F2U(wp[4]);
                uint32_t a3 = F2U(wp[8 * 36 + 4]);
#pragma unroll
                for (int nt = 0; nt < 16; nt++) {
                    const float* hb = xs + (nt >> 3) * 2304 + (k8 * 8 + (lane & 3)) * 72
                                      + (nt & 7) * 8 + (lane >> 2) + t;
                    mma8(d[nt], a0, a1, a2, a3, F2U(hb[0]), F2U(hb[4 * 72]));
                }
            }
        }
    }

    int ocl = OC0 + wid * 16 + (lane >> 2);
#pragma unroll
    for (int nt = 0; nt < 16; nt++) {
        int y = y0 + (nt >> 3);
        int w = (nt & 7) * 8 + (lane & 3) * 2;
        float* p0 = &g_h[(((long)b * CG + ocl) * HH + y) * WW + w];
        *(float2*)p0 = make_float2(d[nt][0], d[nt][1]);
        *(float2*)(p0 + (long)8 * HH * WW) = make_float2(d[nt][2], d[nt][3]);
    }
}

// ---------------------------------------------------------------------------
// Persistent LSTM scan: bf16 m16n8k16 + ldmatrix; h-state stored tap-shifted
// bf16 by the producer (pointwise stage) -> consumer is pure cp.async+mma.
// grid (24, 8) = 192 CTAs, 256 thr, 93.7KB smem -> 2 CTA/SM co-resident.
// smem: wstb bf16 [3t][32m][200] | hpt bf16 [2buf][3t][2bb][32kf][72]
// sbuf (f32 [2][32][68]) overlays hpt buf0.
// ---------------------------------------------------------------------------
#define SCAN_SMEM (38400 + 2 * 27648)

__global__ void __launch_bounds__(256, 2) lstm_scan_mma() {
    extern __shared__ char smc[];
    uint32_t* wstb_u = (uint32_t*)smc;                       // 9600 uints
    char* hpt = smc + 38400;                                 // 2 x 27648 bytes
    float* sbuf = (float*)hpt;                               // overlay buf0
    uint32_t wstb32 = smem_u32(wstb_u);
    uint32_t hpt32 = smem_u32(hpt);

    int tid = threadIdx.x, lane = tid & 31, wid = tid >> 5;
    int ftile = blockIdx.x, bpair = blockIdx.y;
    int F0 = ftile * 8;
    // mma warp tiling
    int m0 = (wid & 1) * 16;
    int wbb = wid >> 2;
    int n0 = ((wid >> 1) & 1) * 32;
    // pointwise mapping
    int pbb = tid >> 7, fl = (tid >> 4) & 7, w0 = (tid & 15) * 4;

    // load weights once (src contiguous, dst stride 100 uints)
    {
        const uint32_t* src = (const uint32_t*)&g_w1rb[(long)ftile * 18432];
#pragma unroll
        for (int j = tid; j < 9216; j += 256)
            wstb_u[(j / 96) * 100 + (j % 96)] = src[j];
    }

    float creg[4] = {0.f, 0.f, 0.f, 0.f};
    float4 hv[4];
    {
        int b = bpair * 2 + pbb;
#pragma unroll
        for (int g = 0; g < 4; g++)
            hv[g] = *(const float4*)&g_h[(((long)(b * CG + g * FEAT_ + F0 + fl)) * HH + 0) * WW + w0];
    }
    __syncthreads();

    unsigned* bar = &g_rowbar[bpair * 32];

    // ldmatrix lane base offsets
    int a_row = (m0 + (lane & 15)) * 200 + ((lane >> 4) << 3);   // halves
    int b_row = (lane & 15);

    for (int y = 0; y < HH; y++) {
        const __nv_bfloat16* hsrc = &g_hsh[y & 1][0][0];

        auto issue_chunk = [&](int ch, int buf) {
            int f0k = ch * 32;
#pragma unroll
            for (int j = 0; j < 6; j++) {
                int i = tid + j * 256;
                int t = i >> 9, r = i & 511, bb = r >> 8, kf = (r >> 3) & 31, w4 = r & 7;
                uint32_t da = hpt32 + buf * 27648
                            + ((((t * 2 + bb) * 32 + kf) * 72) + w4 * 8) * 2;
                const __nv_bfloat16* sa = hsrc + (long)t * HSZ
                            + ((bpair * 2 + bb) * FEAT_ + f0k + kf) * WW + w4 * 8;
                CP_ASYNC16(da, sa);
            }
        };

        float d[4][4];
#pragma unroll
        for (int nt = 0; nt < 4; nt++)
#pragma unroll
            for (int i = 0; i < 4; i++) d[nt][i] = 0.f;

        issue_chunk(0, 0);
        CP_COMMIT();

        for (int ch = 0; ch < 6; ch++) {
            if (ch < 5) { issue_chunk(ch + 1, (ch + 1) & 1); CP_COMMIT(); CP_WAIT1(); }
            else CP_WAIT0();
            __syncthreads();   // hpt[ch&1] ready for all warps

            uint32_t hb_base = hpt32 + (ch & 1) * 27648;
            int kbase = ch * 32;
#pragma unroll
            for (int t = 0; t < 3; t++) {
#pragma unroll
                for (int kk = 0; kk < 2; kk++) {
                    uint32_t a0, a1, a2, a3;
                    uint32_t aaddr = wstb32 + 2 * (t * 6400 + a_row + kbase + kk * 16);
                    LDSM_X4(a0, a1, a2, a3, aaddr);
#pragma unroll
                    for (int nt = 0; nt < 4; nt++) {
                        uint32_t b0, b1;
                        uint32_t baddr = hb_base + 2 * ((((t * 2 + wbb) * 32 + kk * 16 + b_row) * 72)
                                                        + n0 + nt * 8);
                        LDSM_X2T(b0, b1, baddr);
                        mma16(d[nt], a0, a1, a2, a3, b0, b1);
                    }
                }
            }
            __syncthreads();   // mma(buf) done before cp.async reuses buf
        }

        // epilogue: write s to sbuf (overlays hpt buf0; all reads complete)
#pragma unroll
        for (int nt = 0; nt < 4; nt++) {
            int r = m0 + (lane >> 2);
            int cc = n0 + nt * 8 + (lane & 3) * 2;
            *(float2*)&sbuf[wbb * 2176 + r * 68 + cc] = make_float2(d[nt][0], d[nt][1]);
            *(float2*)&sbuf[wbb * 2176 + (r + 8) * 68 + cc] = make_float2(d[nt][2], d[nt][3]);
        }
        __syncthreads();

        // pointwise gate update + tap-shifted bf16 h-state store
        {
            float* sb = sbuf + pbb * 2176;
            float4 ov = *(const float4*)&sb[fl * 68 + w0];
            float4 fv = *(const float4*)&sb[(8 + fl) * 68 + w0];
            float4 iv = *(const float4*)&sb[(16 + fl) * 68 + w0];
            float4 gv = *(const float4*)&sb[(24 + fl) * 68 + w0];
            float so[4] = {sigf(ov.x + hv[0].x), sigf(ov.y + hv[0].y),
                           sigf(ov.z + hv[0].z), sigf(ov.w + hv[0].w)};
            float sf[4] = {sigf(fv.x + hv[1].x), sigf(fv.y + hv[1].y),
                           sigf(fv.z + hv[1].z), sigf(fv.w + hv[1].w)};
            float si[4] = {sigf(iv.x + hv[2].x), sigf(iv.y + hv[2].y),
                           sigf(iv.z + hv[2].z), sigf(iv.w + hv[2].w)};
            float sg[4] = {sigf(gv.x + hv[3].x), sigf(gv.y + hv[3].y),
                           sigf(gv.z + hv[3].z), sigf(gv.w + hv[3].w)};
            float hn[4];
#pragma unroll
            for (int i = 0; i < 4; i++) {
                creg[i] = sf[i] * creg[i] + si[i] * sg[i];
                hn[i] = so[i] * tanhfast(creg[i]);
            }
            // neighbor halo values via shuffle (16 threads per row, contiguous lanes)
            float lft = __shfl_up_sync(0xffffffffu, hn[3], 1);
            float rgt = __shfl_down_sync(0xffffffffu, hn[0], 1);
            if ((tid & 15) == 0) lft = 0.f;
            if ((tid & 15) == 15) rgt = 0.f;

            int b = bpair * 2 + pbb;
            long fbase = ((long)(b * FEAT_ + F0 + fl)) * WW + w0;
            __nv_bfloat16* hbd = &g_hsh[(y & 1) ^ 1][0][0];
            *(uint2*)(hbd + fbase)           = make_uint2(pk2(lft, hn[0]), pk2(hn[1], hn[2]));
            *(uint2*)(hbd + HSZ + fbase)     = make_uint2(pk2(hn[0], hn[1]), pk2(hn[2], hn[3]));
            *(uint2*)(hbd + 2 * HSZ + fbase) = make_uint2(pk2(hn[1], hn[2]), pk2(hn[3], rgt));

            *(float4*)&g_outh[((b * FEAT_ + F0 + fl) * HH + y) * WW + w0] =
                make_float4(tf32r(hn[0]), tf32r(hn[1]), tf32r(hn[2]), tf32r(hn[3]));
        }

        if (y < HH - 1) {
            // prefetch next row's gate inputs
            int b = bpair * 2 + pbb;
#pragma unroll
            for (int g = 0; g < 4; g++)
                hv[g] = *(const float4*)&g_h[(((long)(b * CG + g * FEAT_ + F0 + fl)) * HH + (y + 1)) * WW + w0];
            __syncthreads();   // all h-state stores issued
            if (tid == 0) {
                asm volatile("red.release.gpu.global.add.u32 [%0], %1;" :: "l"(bar), "r"(1u) : "memory");
                unsigned target = 24u * (unsigned)(y + 1);
                unsigned v;
                do {
                    asm volatile("ld.acquire.gpu.global.u32 %0, [%1];" : "=r"(v) : "l"(bar) : "memory");
                } while (v < target);
            }
            __syncthreads();
        }
    }
}

// ---------------------------------------------------------------------------
// skip via mma.sync tf32 (unchanged)
// ---------------------------------------------------------------------------
#define SKIP_SMEM ((4608 + 4608) * 4)

__global__ void __launch_bounds__(256, 2) skip_mma_kernel(const float* __restrict__ x,
                                                          const float* __restrict__ b_skip,
                                                          float* __restrict__ out) {
    extern __shared__ float sm[];
    float* wa = sm;
    float* os = sm + 4608;

    int tid = threadIdx.x, lane = tid & 31, wid = tid >> 5;
    int OC0 = blockIdx.x * 128;
    int b = blockIdx.y >> 5, y0 = (blockIdx.y & 31) * 2;
    int nchunks = (OC0 >> 6) + 2;

    float d[16][4];
#pragma unroll
    for (int nt = 0; nt < 16; nt++)
#pragma unroll
        for (int i = 0; i < 4; i++) d[nt][i] = 0.f;

    const float* ob = g_outh + (long)b * FEAT_ * HH * WW;
    int m0 = wid * 16;

    for (int c = 0; c < nchunks; c++) {
        int k0 = c * 32;
        __syncthreads();
#pragma unroll
        for (int i = tid; i < 1024; i += 256) {
            int oc = i >> 3, kk = i & 7;
            *(float4*)&wa[oc * 36 + kk * 4] =
                *(const float4*)&g_wskt2[(OC0 + oc) * FEAT_ + k0 + kk * 4];
        }
#pragma unroll
        for (int i = tid; i < 1024; i += 256) {
            int yr = i >> 9, r = i & 511, k = r >> 4, w4 = r & 15;
            *(float4*)&os[yr * 2304 + k * 72 + w4 * 4] =
                *(const float4*)&ob[((long)(k0 + k) * HH + y0 + yr) * WW + w4 * 4];
        }
        __syncthreads();
#pragma unroll
        for (int k8 = 0; k8 < 4; k8++) {
            const float* wp = wa + (m0 + (lane >> 2)) * 36 + k8 * 8 + (lane & 3);
            uint32_t a0 = F2U(wp[0]);
            uint32_t a1 = F2U(wp[8 * 36]);
            uint32_t a2 = F2U(wp[4]);
            uint32_t a3 = F2U(wp[8 * 36 + 4]);
#pragma unroll
            for (int nt = 0; nt < 16; nt++) {
                const float* hb = os + (nt >> 3) * 2304 + (k8 * 8 + (lane & 3)) * 72
                                  + (nt & 7) * 8 + (lane >> 2);
                mma8(d[nt], a0, a1, a2, a3, F2U(hb[0]), F2U(hb[4 * 72]));
            }
        }
    }

    int ocl = OC0 + wid * 16 + (lane >> 2);
    float bs0 = b_skip[ocl], bs1 = b_skip[ocl + 8];
#pragma unroll
    for (int nt = 0; nt < 16; nt++) {
        int y = y0 + (nt >> 3);
        int w = (nt & 7) * 8 + (lane & 3) * 2;
        long off = ((long)(b * CIN_ + ocl) * HH + y) * WW + w;
        float2 xv = *(const float2*)&x[off];
        *(float2*)&out[off] = make_float2(d[nt][0] + xv.x + bs0, d[nt][1] + xv.y + bs0);
        long off2 = off + (long)8 * HH * WW;
        float2 xv2 = *(const float2*)&x[off2];
        *(float2*)&out[off2] = make_float2(d[nt][2] + xv2.x + bs1, d[nt][3] + xv2.y + bs1);
    }
}

// ---------------------------------------------------------------------------
extern "C" void kernel_launch(void* const* d_in, const int* in_sizes, int n_in,
                              void* d_out, int out_size) {
    const float* x      = (const float*)d_in[0];
    const float* w_i2s  = (const float*)d_in[1];
    const float* w_s2s  = (const float*)d_in[2];
    const float* w_skip = (const float*)d_in[3];
    const float* b_skip = (const float*)d_in[4];
    float* out = (float*)d_out;

    cudaFuncSetAttribute(i2s_mma_kernel, cudaFuncAttributeMaxDynamicSharedMemorySize, I2S_SMEM);
    cudaFuncSetAttribute(lstm_scan_mma, cudaFuncAttributeMaxDynamicSharedMemorySize, SCAN_SMEM);
    cudaFuncSetAttribute(skip_mma_kernel, cudaFuncAttributeMaxDynamicSharedMemorySize, SKIP_SMEM);

    prep_kernel<<<(24 * 3 * 32 * 192 + 255) / 256, 256>>>(w_i2s, w_s2s, w_skip);
    init_kernel<<<(3 * HSZ / 2 + 255) / 256, 256>>>();
    i2s_mma_kernel<<<dim3(6, 512), 256, I2S_SMEM>>>(x);
    lstm_scan_mma<<<dim3(24, 8), 256, SCAN_SMEM>>>();
    skip_mma_kernel<<<dim3(3, 512), 256, SKIP_SMEM>>>(x, b_skip, out);
}

// round 8
// speedup vs baseline: 4.6181x; 1.1087x over previous
#include <cuda_runtime.h>
#include <cuda_bf16.h>
#include <math.h>
#include <stdint.h>

#define NB    16
#define CIN_  384
#define CG    768
#define FEAT_ 192
#define HH    64
#define WW    64
#define HSZ   (NB * FEAT_ * WW)

// Scratch (device globals; no allocations allowed)
__device__ float g_h[NB * CG * HH * WW];            // shuffled gate inputs (b, c', y, w)
__device__ float g_Wa[2][CG * CIN_];                // i2s weights [tap][oc'][ic], tf32-rounded
__device__ __nv_bfloat16 g_w1rb[24 * 3 * 32 * 192]; // s2s weights [ftile][t][ocr][kf], bf16
__device__ float g_wskt2[CIN_ * FEAT_];             // skip weights [co][ci], tf32-rounded
__device__ __nv_bfloat16 g_hsh[2][3][HSZ];          // hidden, tap-shifted bf16, double buffered
__device__ float g_outh[NB * FEAT_ * HH * WW];      // scan outputs (tf32-rounded)
__device__ unsigned g_rowbar[NB * 32];              // per-bpair row barriers

__device__ __forceinline__ float sigf(float v) { return 1.0f / (1.0f + __expf(-v)); }
__device__ __forceinline__ float tanhfast(float x) {
    float y; asm("tanh.approx.f32 %0, %1;" : "=f"(y) : "f"(x)); return y;
}
__device__ __forceinline__ float tf32r(float x) {
    uint32_t u; asm("cvt.rna.tf32.f32 %0, %1;" : "=r"(u) : "f"(x));
    return __uint_as_float(u);
}
__device__ __forceinline__ uint32_t smem_u32(const void* p) {
    uint32_t a;
    asm("{ .reg .u64 t; cvta.to.shared.u64 t, %1; cvt.u32.u64 %0, t; }" : "=r"(a) : "l"(p));
    return a;
}
// pack two f32 -> bf16x2 (lo = first arg, hi = second)
__device__ __forceinline__ uint32_t pk2(float lo, float hi) {
    uint32_t r; asm("cvt.rn.bf16x2.f32 %0, %1, %2;" : "=r"(r) : "f"(hi), "f"(lo));
    return r;
}
#define F2U(x) __float_as_uint(x)
#define CP_ASYNC16(dst, src) \
    asm volatile("cp.async.cg.shared.global [%0], [%1], 16;" :: "r"(dst), "l"(src) : "memory")
#define CP_COMMIT() asm volatile("cp.async.commit_group;" ::: "memory")
#define CP_WAIT1()  asm volatile("cp.async.wait_group 1;" ::: "memory")
#define CP_WAIT0()  asm volatile("cp.async.wait_group 0;" ::: "memory")

// tf32 m16n8k8 (i2s / skip)
__device__ __forceinline__ void mma8(float* d, uint32_t a0, uint32_t a1, uint32_t a2, uint32_t a3,
                                     uint32_t b0, uint32_t b1) {
    asm volatile("mma.sync.aligned.m16n8k8.row.col.f32.tf32.tf32.f32 "
                 "{%0,%1,%2,%3}, {%4,%5,%6,%7}, {%8,%9}, {%0,%1,%2,%3};"
                 : "+f"(d[0]), "+f"(d[1]), "+f"(d[2]), "+f"(d[3])
                 : "r"(a0), "r"(a1), "r"(a2), "r"(a3), "r"(b0), "r"(b1));
}
// bf16 m16n8k16 (scan)
__device__ __forceinline__ void mma16(float* d, uint32_t a0, uint32_t a1, uint32_t a2, uint32_t a3,
                                      uint32_t b0, uint32_t b1) {
    asm volatile("mma.sync.aligned.m16n8k16.row.col.f32.bf16.bf16.f32 "
                 "{%0,%1,%2,%3}, {%4,%5,%6,%7}, {%8,%9}, {%0,%1,%2,%3};"
                 : "+f"(d[0]), "+f"(d[1]), "+f"(d[2]), "+f"(d[3])
                 : "r"(a0), "r"(a1), "r"(a2), "r"(a3), "r"(b0), "r"(b1));
}
#define LDSM_X4(r0, r1, r2, r3, a) \
    asm volatile("ldmatrix.sync.aligned.m8n8.x4.shared.b16 {%0,%1,%2,%3}, [%4];" \
                 : "=r"(r0), "=r"(r1), "=r"(r2), "=r"(r3) : "r"(a))
#define LDSM_X4T(r0, r1, r2, r3, a) \
    asm volatile("ldmatrix.sync.aligned.m8n8.x4.trans.shared.b16 {%0,%1,%2,%3}, [%4];" \
                 : "=r"(r0), "=r"(r1), "=r"(r2), "=r"(r3) : "r"(a))

// ---------------------------------------------------------------------------
// Weight prep
// ---------------------------------------------------------------------------
__global__ void prep_kernel(const float* __restrict__ w_i2s,
                            const float* __restrict__ w_s2s,
                            const float* __restrict__ w_skip) {
    int idx = blockIdx.x * blockDim.x + threadIdx.x;
    if (idx < CG * CIN_) {
        int ocp = idx / CIN_, ic = idx % CIN_;
        int q = ocp / 192, p = (ocp % 192) / 64, fl = ocp % 64;
        int c = p * 256 + q * 64 + fl;
        const float* wb = w_i2s + ((long)c * CIN_ + ic) * 3;
        g_Wa[0][idx] = tf32r(wb[0]);
        g_Wa[1][idx] = (p >= (ic / 128)) ? tf32r(wb[1]) : 0.f;
    }
    if (idx < 24 * 3 * 32 * 192) {                   // bf16 s2s: [ftile][t][ocr][kf]
        int ftile = idx / 18432;
        int r2 = idx % 18432;
        int t = r2 / 6144;
        int r3 = r2 % 6144;
        int ocr = r3 / 192, kf = r3 % 192;
        int gate = ocr >> 3, j = ocr & 7;
        int oc = gate * FEAT_ + ftile * 8 + j;
        g_w1rb[idx] = __float2bfloat16(w_s2s[((long)oc * FEAT_ + kf) * 3 + t]);
    }
    if (idx < CIN_ * FEAT_) {
        g_wskt2[idx] = tf32r(w_skip[idx]);
    }
}

__global__ void init_kernel() {
    int i = blockIdx.x * blockDim.x + threadIdx.x;
    if (i < 3 * HSZ / 2) ((uint32_t*)&g_hsh[0][0][0])[i] = 0u;   // zero parity-0 state
    if (i < NB * 32) g_rowbar[i] = 0u;
}

// ---------------------------------------------------------------------------
// i2s via mma.sync tf32 (unchanged)
// ---------------------------------------------------------------------------
#define I2S_SMEM 55296

__global__ void __launch_bounds__(256, 2) i2s_mma_kernel(const float* __restrict__ x) {
    extern __shared__ float sm[];
    float* wa = sm;               // [t][oc][kk] stride 36
    float* xs = sm + 9216;        // [yr][k][i] stride 72, i=w+1 (halo at 0)

    int tid = threadIdx.x, lane = tid & 31, wid = tid >> 5;
    int OC0 = blockIdx.x * 128;
    int b = blockIdx.y >> 5, y0 = (blockIdx.y & 31) * 2;

    if (tid < 64) xs[(tid >> 5) * 2304 + (tid & 31) * 72] = 0.f;

    float d[16][4];
#pragma unroll
    for (int nt = 0; nt < 16; nt++)
#pragma unroll
        for (int i = 0; i < 4; i++) d[nt][i] = 0.f;

    const float* xb = x + (long)b * CIN_ * HH * WW;
    int m0 = wid * 16;

    for (int c = 0; c < 12; c++) {
        int k0 = c * 32;
        __syncthreads();
#pragma unroll
        for (int i = tid; i < 2048; i += 256) {
            int t = i >> 10, r = i & 1023, oc = r >> 3, kk = r & 7;
            float4 v = *(const float4*)&g_Wa[t][(OC0 + oc) * CIN_ + k0 + kk * 4];
            *(float4*)&wa[t * 4608 + oc * 36 + kk * 4] = v;
        }
#pragma unroll
        for (int i = tid; i < 4096; i += 256) {
            int yr = i >> 11, r = i & 2047, k = r >> 6, w = r & 63;
            float v = xb[((long)(k0 + k) * HH + y0 + yr) * WW + w];
            xs[yr * 2304 + k * 72 + w + 1] = tf32r(v);
        }
        __syncthreads();
#pragma unroll
        for (int k8 = 0; k8 < 4; k8++) {
#pragma unroll
            for (int t = 0; t < 2; t++) {
                const float* wp = wa + t * 4608 + (m0 + (lane >> 2)) * 36 + k8 * 8 + (lane & 3);
                uint32_t a0 = F2U(wp[0]);
                uint32_t a1 = F2U(wp[8 * 36]);
                uint32_t a2 = F2U(wp[4]);
                uint32_t a3 = F2U(wp[8 * 36 + 4]);
#pragma unroll
                for (int nt = 0; nt < 16; nt++) {
                    const float* hb = xs + (nt >> 3) * 2304 + (k8 * 8 + (lane & 3)) * 72
                                      + (nt & 7) * 8 + (lane >> 2) + t;
                    mma8(d[nt], a0, a1, a2, a3, F2U(hb[0]), F2U(hb[4 * 72]));
                }
            }
        }
    }

    int ocl = OC0 + wid * 16 + (lane >> 2);
#pragma unroll
    for (int nt = 0; nt < 16; nt++) {
        int y = y0 + (nt >> 3);
        int w = (nt & 7) * 8 + (lane & 3) * 2;
        float* p0 = &g_h[(((long)b * CG + ocl) * HH + y) * WW + w];
        *(float2*)p0 = make_float2(d[nt][0], d[nt][1]);
        *(float2*)(p0 + (long)8 * HH * WW) = make_float2(d[nt][2], d[nt][3]);
    }
}

// ---------------------------------------------------------------------------
// Persistent LSTM scan: bf16 m16n8k16 + ldmatrix.x4; 3-stage cp.async ring
// (one __syncthreads per chunk); swizzled B tiles (stride 64 halves + XOR).
// grid (24, 8) = 192 CTAs, 256 thr, 109.5KB smem -> 2 CTA/SM co-resident.
// smem: wstb bf16 [3t][32m][200] | hpt bf16 3 bufs x [3t][2bb][32kf][64] swz
// sbuf (f32 [2][32][68]) overlays hpt buf0.
// ---------------------------------------------------------------------------
#define SCAN_SMEM (38400 + 3 * 24576)

__global__ void __launch_bounds__(256, 2) lstm_scan_mma() {
    extern __shared__ char smc[];
    uint32_t* wstb_u = (uint32_t*)smc;                       // 9600 uints
    char* hpt = smc + 38400;                                 // 3 x 24576 bytes
    float* sbuf = (float*)hpt;                               // overlay buf0
    uint32_t wstb32 = smem_u32(wstb_u);
    uint32_t hpt32 = smem_u32(hpt);

    int tid = threadIdx.x, lane = tid & 31, wid = tid >> 5;
    int ftile = blockIdx.x, bpair = blockIdx.y;
    int F0 = ftile * 8;
    // mma warp tiling
    int m0 = (wid & 1) * 16;
    int wbb = wid >> 2;
    int n0 = ((wid >> 1) & 1) * 32;
    // pointwise mapping
    int pbb = tid >> 7, fl = (tid >> 4) & 7, w0 = (tid & 15) * 4;

    // load weights once (src contiguous, dst stride 100 uints)
    {
        const uint32_t* src = (const uint32_t*)&g_w1rb[(long)ftile * 18432];
#pragma unroll
        for (int j = tid; j < 9216; j += 256)
            wstb_u[(j / 96) * 100 + (j % 96)] = src[j];
    }

    float creg[4] = {0.f, 0.f, 0.f, 0.f};
    float4 hv[4];
    {
        int b = bpair * 2 + pbb;
#pragma unroll
        for (int g = 0; g < 4; g++)
            hv[g] = *(const float4*)&g_h[(((long)(b * CG + g * FEAT_ + F0 + fl)) * HH + 0) * WW + w0];
    }
    __syncthreads();

    unsigned* bar = &g_rowbar[bpair * 32];

    // ldmatrix lane constants
    int a_row = (m0 + (lane & 15)) * 200 + ((lane >> 4) << 3);   // A (halves)
    int kfl  = (lane & 7) + (lane & 8);                          // B row-in-tile 0..15
    int swz  = (lane & 7) << 4;                                  // B XOR swizzle (bytes)
    int col8 = (lane & 16) ? 8 : 0;                              // B n-subblock

    for (int y = 0; y < HH; y++) {
        const __nv_bfloat16* hsrc = &g_hsh[y & 1][0][0];

        auto issue_chunk = [&](int ch, int buf) {
            int f0k = ch * 32;
            uint32_t dbase = hpt32 + buf * 24576;
#pragma unroll
            for (int j = 0; j < 6; j++) {
                int i = tid + j * 256;
                int t = i >> 9, r = i & 511, bb = r >> 8, kf = (r >> 3) & 31, w4 = r & 7;
                uint32_t da = dbase + (((t * 2 + bb) * 32 + kf) << 7)
                            + ((w4 * 16) ^ ((kf & 7) << 4));
                const __nv_bfloat16* sa = hsrc + (long)t * HSZ
                            + ((bpair * 2 + bb) * FEAT_ + f0k + kf) * WW + w4 * 8;
                CP_ASYNC16(da, sa);
            }
        };

        float d[4][4];
#pragma unroll
        for (int nt = 0; nt < 4; nt++)
#pragma unroll
            for (int i = 0; i < 4; i++) d[nt][i] = 0.f;

        issue_chunk(0, 0); CP_COMMIT();
        issue_chunk(1, 1); CP_COMMIT();

#pragma unroll
        for (int ch = 0; ch < 6; ch++) {
            if (ch < 5) CP_WAIT1(); else CP_WAIT0();
            __syncthreads();                 // chunk ch visible to all; mma(ch-1) done by all
            if (ch < 4) { issue_chunk(ch + 2, (ch + 2) % 3); CP_COMMIT(); }

            uint32_t hb = hpt32 + (ch % 3) * 24576;
            int kbase = ch * 32;
#pragma unroll
            for (int t = 0; t < 3; t++) {
#pragma unroll
                for (int kk = 0; kk < 2; kk++) {
                    uint32_t a0, a1, a2, a3;
                    uint32_t aaddr = wstb32 + 2 * (t * 6400 + a_row + kbase + kk * 16);
                    LDSM_X4(a0, a1, a2, a3, aaddr);
                    uint32_t rowoff = (uint32_t)(((t * 2 + wbb) * 32 + kk * 16 + kfl) << 7);
#pragma unroll
                    for (int nt2 = 0; nt2 < 2; nt2++) {
                        uint32_t b0, b1, b2, b3;
                        uint32_t baddr = hb + rowoff
                                       + ((uint32_t)((n0 + nt2 * 16 + col8) * 2) ^ (uint32_t)swz);
                        LDSM_X4T(b0, b1, b2, b3, baddr);
                        mma16(d[nt2 * 2],     a0, a1, a2, a3, b0, b1);
                        mma16(d[nt2 * 2 + 1], a0, a1, a2, a3, b2, b3);
                    }
                }
            }
        }

        // epilogue: write s to sbuf (overlays hpt buf0; buf0 reads done by iter-4 sync)
#pragma unroll
        for (int nt = 0; nt < 4; nt++) {
            int r = m0 + (lane >> 2);
            int cc = n0 + nt * 8 + (lane & 3) * 2;
            *(float2*)&sbuf[wbb * 2176 + r * 68 + cc] = make_float2(d[nt][0], d[nt][1]);
            *(float2*)&sbuf[wbb * 2176 + (r + 8) * 68 + cc] = make_float2(d[nt][2], d[nt][3]);
        }
        __syncthreads();

        // pointwise gate update + tap-shifted bf16 h-state store
        {
            float* sb = sbuf + pbb * 2176;
            float4 ov = *(const float4*)&sb[fl * 68 + w0];
            float4 fv = *(const float4*)&sb[(8 + fl) * 68 + w0];
            float4 iv = *(const float4*)&sb[(16 + fl) * 68 + w0];
            float4 gv = *(const float4*)&sb[(24 + fl) * 68 + w0];
            float so[4] = {sigf(ov.x + hv[0].x), sigf(ov.y + hv[0].y),
                           sigf(ov.z + hv[0].z), sigf(ov.w + hv[0].w)};
            float sf[4] = {sigf(fv.x + hv[1].x), sigf(fv.y + hv[1].y),
                           sigf(fv.z + hv[1].z), sigf(fv.w + hv[1].w)};
            float si[4] = {sigf(iv.x + hv[2].x), sigf(iv.y + hv[2].y),
                           sigf(iv.z + hv[2].z), sigf(iv.w + hv[2].w)};
            float sg[4] = {sigf(gv.x + hv[3].x), sigf(gv.y + hv[3].y),
                           sigf(gv.z + hv[3].z), sigf(gv.w + hv[3].w)};
            float hn[4];
#pragma unroll
            for (int i = 0; i < 4; i++) {
                creg[i] = sf[i] * creg[i] + si[i] * sg[i];
                hn[i] = so[i] * tanhfast(creg[i]);
            }
            float lft = __shfl_up_sync(0xffffffffu, hn[3], 1);
            float rgt = __shfl_down_sync(0xffffffffu, hn[0], 1);
            if ((tid & 15) == 0) lft = 0.f;
            if ((tid & 15) == 15) rgt = 0.f;

            int b = bpair * 2 + pbb;
            long fbase = ((long)(b * FEAT_ + F0 + fl)) * WW + w0;
            __nv_bfloat16* hbd = &g_hsh[(y & 1) ^ 1][0][0];
            *(uint2*)(hbd + fbase)           = make_uint2(pk2(lft, hn[0]), pk2(hn[1], hn[2]));
            *(uint2*)(hbd + HSZ + fbase)     = make_uint2(pk2(hn[0], hn[1]), pk2(hn[2], hn[3]));
            *(uint2*)(hbd + 2 * HSZ + fbase) = make_uint2(pk2(hn[1], hn[2]), pk2(hn[3], rgt));

            *(float4*)&g_outh[((b * FEAT_ + F0 + fl) * HH + y) * WW + w0] =
                make_float4(tf32r(hn[0]), tf32r(hn[1]), tf32r(hn[2]), tf32r(hn[3]));
        }

        if (y < HH - 1) {
            // prefetch next row's gate inputs (hides HBM behind barrier)
            int b = bpair * 2 + pbb;
#pragma unroll
            for (int g = 0; g < 4; g++)
                hv[g] = *(const float4*)&g_h[(((long)(b * CG + g * FEAT_ + F0 + fl)) * HH + (y + 1)) * WW + w0];
            __syncthreads();   // all h-state stores issued
            if (tid == 0) {
                asm volatile("red.release.gpu.global.add.u32 [%0], %1;" :: "l"(bar), "r"(1u) : "memory");
                unsigned target = 24u * (unsigned)(y + 1);
                unsigned v;
                do {
                    asm volatile("ld.acquire.gpu.global.u32 %0, [%1];" : "=r"(v) : "l"(bar) : "memory");
                } while (v < target);
            }
            __syncthreads();
        }
    }
}

// ---------------------------------------------------------------------------
// skip via mma.sync tf32 (unchanged)
// ---------------------------------------------------------------------------
#define SKIP_SMEM ((4608 + 4608) * 4)

__global__ void __launch_bounds__(256, 2) skip_mma_kernel(const float* __restrict__ x,
                                                          const float* __restrict__ b_skip,
                                                          float* __restrict__ out) {
    extern __shared__ float sm[];
    float* wa = sm;
    float* os = sm + 4608;

    int tid = threadIdx.x, lane = tid & 31, wid = tid >> 5;
    int OC0 = blockIdx.x * 128;
    int b = blockIdx.y >> 5, y0 = (blockIdx.y & 31) * 2;
    int nchunks = (OC0 >> 6) + 2;

    float d[16][4];
#pragma unroll
    for (int nt = 0; nt < 16; nt++)
#pragma unroll
        for (int i = 0; i < 4; i++) d[nt][i] = 0.f;

    const float* ob = g_outh + (long)b * FEAT_ * HH * WW;
    int m0 = wid * 16;

    for (int c = 0; c < nchunks; c++) {
        int k0 = c * 32;
        __syncthreads();
#pragma unroll
        for (int i = tid; i < 1024; i += 256) {
            int oc = i >> 3, kk = i & 7;
            *(float4*)&wa[oc * 36 + kk * 4] =
                *(const float4*)&g_wskt2[(OC0 + oc) * FEAT_ + k0 + kk * 4];
        }
#pragma unroll
        for (int i = tid; i < 1024; i += 256) {
            int yr = i >> 9, r = i & 511, k = r >> 4, w4 = r & 15;
            *(float4*)&os[yr * 2304 + k * 72 + w4 * 4] =
                *(const float4*)&ob[((long)(k0 + k) * HH + y0 + yr) * WW + w4 * 4];
        }
        __syncthreads();
#pragma unroll
        for (int k8 = 0; k8 < 4; k8++) {
            const float* wp = wa + (m0 + (lane >> 2)) * 36 + k8 * 8 + (lane & 3);
            uint32_t a0 = F2U(wp[0]);
            uint32_t a1 = F2U(wp[8 * 36]);
            uint32_t a2 = F2U(wp[4]);
            uint32_t a3 = F2U(wp[8 * 36 + 4]);
#pragma unroll
            for (int nt = 0; nt < 16; nt++) {
                const float* hb = os + (nt >> 3) * 2304 + (k8 * 8 + (lane & 3)) * 72
                                  + (nt & 7) * 8 + (lane >> 2);
                mma8(d[nt], a0, a1, a2, a3, F2U(hb[0]), F2U(hb[4 * 72]));
            }
        }
    }

    int ocl = OC0 + wid * 16 + (lane >> 2);
    float bs0 = b_skip[ocl], bs1 = b_skip[ocl + 8];
#pragma unroll
    for (int nt = 0; nt < 16; nt++) {
        int y = y0 + (nt >> 3);
        int w = (nt & 7) * 8 + (lane & 3) * 2;
        long off = ((long)(b * CIN_ + ocl) * HH + y) * WW + w;
        float2 xv = *(const float2*)&x[off];
        *(float2*)&out[off] = make_float2(d[nt][0] + xv.x + bs0, d[nt][1] + xv.y + bs0);
        long off2 = off + (long)8 * HH * WW;
        float2 xv2 = *(const float2*)&x[off2];
        *(float2*)&out[off2] = make_float2(d[nt][2] + xv2.x + bs1, d[nt][3] + xv2.y + bs1);
    }
}

// ---------------------------------------------------------------------------
extern "C" void kernel_launch(void* const* d_in, const int* in_sizes, int n_in,
                              void* d_out, int out_size) {
    const float* x      = (const float*)d_in[0];
    const float* w_i2s  = (const float*)d_in[1];
    const float* w_s2s  = (const float*)d_in[2];
    const float* w_skip = (const float*)d_in[3];
    const float* b_skip = (const float*)d_in[4];
    float* out = (float*)d_out;

    cudaFuncSetAttribute(i2s_mma_kernel, cudaFuncAttributeMaxDynamicSharedMemorySize, I2S_SMEM);
    cudaFuncSetAttribute(lstm_scan_mma, cudaFuncAttributeMaxDynamicSharedMemorySize, SCAN_SMEM);
    cudaFuncSetAttribute(skip_mma_kernel, cudaFuncAttributeMaxDynamicSharedMemorySize, SKIP_SMEM);

    prep_kernel<<<(24 * 3 * 32 * 192 + 255) / 256, 256>>>(w_i2s, w_s2s, w_skip);
    init_kernel<<<(3 * HSZ / 2 + 255) / 256, 256>>>();
    i2s_mma_kernel<<<dim3(6, 512), 256, I2S_SMEM>>>(x);
    lstm_scan_mma<<<dim3(24, 8), 256, SCAN_SMEM>>>();
    skip_mma_kernel<<<dim3(3, 512), 256, SKIP_SMEM>>>(x, b_skip, out);
}